// round 2
// baseline (speedup 1.0000x reference)
#include <cuda_runtime.h>

#define D_MODEL 1024
#define H 16
#define DK 64
#define DV 64
#define BATCH 4
#define SEQ 8192
#define MTOT (BATCH * SEQ)

// ---------------- scratch (device globals: no allocations allowed) ----------
__device__ float g_q[(size_t)MTOT * D_MODEL];                 // 128 MB
__device__ float g_k[(size_t)MTOT * D_MODEL];                 // 128 MB
__device__ float g_v[(size_t)MTOT * D_MODEL];                 // 128 MB
__device__ float g_kv[BATCH * H * DK * DV];                   // 1 MB
__device__ float g_w2t[(size_t)BATCH * D_MODEL * D_MODEL];    // 16 MB

// ---------------- tiled fp32 GEMM: C = A @ B^T + bias -----------------------
// A: [M, 1024] row-major, B: [1024, 1024] row-major (N,K), C: [M, 1024]
#define BM 128
#define BN 128
#define BK 16
#define TM 8
#define TN 8
#define SSTR (BM + 4)   // 132: 16B-aligned fragment loads, low-conflict stores

__device__ __forceinline__ void gemm_abt_bias(
    const float* __restrict__ A,
    const float* __restrict__ Bw,
    const float* __restrict__ bias,
    float* __restrict__ C,
    int bm, int bn)
{
    __shared__ float As[BK][SSTR];
    __shared__ float Bs[BK][SSTR];
    const int tid = threadIdx.x;
    const int tx = tid & 15;
    const int ty = tid >> 4;

    float acc[TM][TN];
#pragma unroll
    for (int i = 0; i < TM; i++)
#pragma unroll
        for (int j = 0; j < TN; j++) acc[i][j] = 0.f;

    for (int k0 = 0; k0 < D_MODEL; k0 += BK) {
#pragma unroll
        for (int u = 0; u < 2; u++) {
            int l   = tid + u * 256;      // 512 float4 loads per operand
            int row = l >> 2;             // 0..127
            int c   = (l & 3) << 2;       // 0,4,8,12
            float4 a = *reinterpret_cast<const float4*>(
                A + (size_t)(bm + row) * D_MODEL + k0 + c);
            As[c + 0][row] = a.x; As[c + 1][row] = a.y;
            As[c + 2][row] = a.z; As[c + 3][row] = a.w;
            float4 b = *reinterpret_cast<const float4*>(
                Bw + (size_t)(bn + row) * D_MODEL + k0 + c);
            Bs[c + 0][row] = b.x; Bs[c + 1][row] = b.y;
            Bs[c + 2][row] = b.z; Bs[c + 3][row] = b.w;
        }
        __syncthreads();
#pragma unroll
        for (int kk = 0; kk < BK; kk++) {
            float ar[TM], br[TN];
            *reinterpret_cast<float4*>(ar)     = *reinterpret_cast<const float4*>(&As[kk][ty * TM]);
            *reinterpret_cast<float4*>(ar + 4) = *reinterpret_cast<const float4*>(&As[kk][ty * TM + 4]);
            *reinterpret_cast<float4*>(br)     = *reinterpret_cast<const float4*>(&Bs[kk][tx * TN]);
            *reinterpret_cast<float4*>(br + 4) = *reinterpret_cast<const float4*>(&Bs[kk][tx * TN + 4]);
#pragma unroll
            for (int i = 0; i < TM; i++)
#pragma unroll
                for (int j = 0; j < TN; j++)
                    acc[i][j] += ar[i] * br[j];
        }
        __syncthreads();
    }

#pragma unroll
    for (int i = 0; i < TM; i++) {
        int row = bm + ty * TM + i;
#pragma unroll
        for (int j4 = 0; j4 < TN; j4 += 4) {
            int col = bn + tx * TN + j4;
            float4 o;
            o.x = acc[i][j4 + 0] + bias[col + 0];
            o.y = acc[i][j4 + 1] + bias[col + 1];
            o.z = acc[i][j4 + 2] + bias[col + 2];
            o.w = acc[i][j4 + 3] + bias[col + 3];
            *reinterpret_cast<float4*>(C + (size_t)row * D_MODEL + col) = o;
        }
    }
}

// ---------------- K1: fused QKV projection (grid.z selects which) -----------
__global__ void __launch_bounds__(256) proj_kernel(
    const float* __restrict__ q_in, const float* __restrict__ k_in,
    const float* __restrict__ v_in,
    const float* __restrict__ Wq, const float* __restrict__ bq,
    const float* __restrict__ Wk, const float* __restrict__ bk,
    const float* __restrict__ Wv, const float* __restrict__ bv)
{
    int which = blockIdx.z;
    const float* A    = (which == 0) ? q_in : (which == 1) ? k_in : v_in;
    const float* W    = (which == 0) ? Wq   : (which == 1) ? Wk   : Wv;
    const float* bias = (which == 0) ? bq   : (which == 1) ? bk   : bv;
    float* C          = (which == 0) ? g_q  : (which == 1) ? g_k  : g_v;
    gemm_abt_bias(A, W, bias, C, blockIdx.y * BM, blockIdx.x * BN);
}

// ---------------- K0: zero kv accumulator ------------------------------------
__global__ void zero_kv_kernel()
{
    int i = blockIdx.x * blockDim.x + threadIdx.x;
    if (i < BATCH * H * DK * DV) g_kv[i] = 0.f;
}

// ---------------- K2: kv[b,h] = sum_n k[b,n,h,:] (x) v[b,n,h,:] --------------
#define NCHUNK 16
#define CHUNK (SEQ / NCHUNK)   // 512

__global__ void __launch_bounds__(256) kv_kernel()
{
    const int bh = blockIdx.x;           // 0..63
    const int chunk = blockIdx.y;        // 0..15
    const int b = bh >> 4, h = bh & 15;

    const float* kbase = g_k + (size_t)b * SEQ * D_MODEL + h * DK;
    const float* vbase = g_v + (size_t)b * SEQ * D_MODEL + h * DK;

    __shared__ float ks[8][64];
    __shared__ float vs[8][64];

    const int tid = threadIdx.x;
    const int tj = tid & 15, ti = tid >> 4;
    float acc[4][4];
#pragma unroll
    for (int i = 0; i < 4; i++)
#pragma unroll
        for (int j = 0; j < 4; j++) acc[i][j] = 0.f;

    const int n0 = chunk * CHUNK;
    for (int nn = n0; nn < n0 + CHUNK; nn += 8) {
        // 256 threads load 256 float4: first 128 -> ks, rest -> vs
        int l   = tid & 127;
        int row = l >> 4;
        int c   = (l & 15) << 2;
        const float* src = (tid < 128) ? kbase : vbase;
        float* dst = (tid < 128) ? &ks[row][c] : &vs[row][c];
        *reinterpret_cast<float4*>(dst) =
            *reinterpret_cast<const float4*>(src + (size_t)(nn + row) * D_MODEL + c);
        __syncthreads();
#pragma unroll
        for (int r = 0; r < 8; r++) {
            float kr[4], vr[4];
            *reinterpret_cast<float4*>(kr) = *reinterpret_cast<const float4*>(&ks[r][ti * 4]);
            *reinterpret_cast<float4*>(vr) = *reinterpret_cast<const float4*>(&vs[r][tj * 4]);
#pragma unroll
            for (int i = 0; i < 4; i++)
#pragma unroll
                for (int j = 0; j < 4; j++)
                    acc[i][j] += kr[i] * vr[j];
        }
        __syncthreads();
    }

    float* kvp = g_kv + (size_t)bh * DK * DV;
#pragma unroll
    for (int i = 0; i < 4; i++)
#pragma unroll
        for (int j = 0; j < 4; j++)
            atomicAdd(&kvp[(ti * 4 + i) * DV + tj * 4 + j], acc[i][j]);
}

// ---------------- K3: xnorm(kv) + fold into W2T[b] ---------------------------
// W2T[b][j][h*64+i] = sum_d kv_n[b,h,i,d] * Wo[j, h*64+d]
__global__ void __launch_bounds__(256) fold_kernel(
    const float* __restrict__ Wo, const float* __restrict__ gamma)
{
    const int bh = blockIdx.x;
    const int b = bh >> 4, h = bh & 15;

    __shared__ float kvn[64][65];
    __shared__ float rn[64];

    const int tid = threadIdx.x;
    const float* kvsrc = g_kv + (size_t)bh * DK * DV;
    for (int l = tid; l < 64 * 64; l += 256)
        kvn[l >> 6][l & 63] = kvsrc[l];
    __syncthreads();

    if (tid < 64) {
        float s = 0.f;
#pragma unroll 8
        for (int d = 0; d < 64; d++) { float x = kvn[tid][d]; s += x * x; }
        rn[tid] = gamma[h] * rsqrtf(s);
    }
    __syncthreads();
    for (int l = tid; l < 64 * 64; l += 256) {
        int i = l >> 6;
        kvn[i][l & 63] *= rn[i];
    }
    __syncthreads();

    const int grp = tid >> 6;   // 0..3
    const int i   = tid & 63;
    float* w2t = g_w2t + (size_t)b * D_MODEL * D_MODEL;
    for (int j = grp; j < D_MODEL; j += 4) {
        const float* wr = Wo + (size_t)j * D_MODEL + h * DK;
        float acc = 0.f;
#pragma unroll 8
        for (int d = 0; d < 64; d++)
            acc += kvn[i][d] * wr[d];
        w2t[(size_t)j * D_MODEL + h * DK + i] = acc;
    }
}

// ---------------- K4: q xnorm in place ---------------------------------------
__global__ void __launch_bounds__(256) qnorm_kernel(const float* __restrict__ gamma)
{
    const size_t rowbase = (size_t)blockIdx.x * D_MODEL;
    const int t = threadIdx.x;
    float4 x = *reinterpret_cast<const float4*>(g_q + rowbase + t * 4);
    float s = x.x * x.x + x.y * x.y + x.z * x.z + x.w * x.w;
    // 16-lane groups == one 64-col head
    s += __shfl_xor_sync(0xffffffffu, s, 1);
    s += __shfl_xor_sync(0xffffffffu, s, 2);
    s += __shfl_xor_sync(0xffffffffu, s, 4);
    s += __shfl_xor_sync(0xffffffffu, s, 8);
    float sc = gamma[t >> 4] * rsqrtf(s);
    x.x *= sc; x.y *= sc; x.z *= sc; x.w *= sc;
    *reinterpret_cast<float4*>(g_q + rowbase + t * 4) = x;
}

// ---------------- K5: out[b] = q_n[b] @ W2T[b]^T + bo ------------------------
__global__ void __launch_bounds__(256) out_kernel(
    const float* __restrict__ bo, float* __restrict__ out)
{
    const int b = blockIdx.z;
    gemm_abt_bias(g_q   + (size_t)b * SEQ * D_MODEL,
                  g_w2t + (size_t)b * D_MODEL * D_MODEL,
                  bo,
                  out   + (size_t)b * SEQ * D_MODEL,
                  blockIdx.y * BM, blockIdx.x * BN);
}

// ---------------- launch ------------------------------------------------------
extern "C" void kernel_launch(void* const* d_in, const int* in_sizes, int n_in,
                              void* d_out, int out_size)
{
    const float* queries = (const float*)d_in[0];
    const float* keys    = (const float*)d_in[1];
    const float* values  = (const float*)d_in[2];
    const float* Wq = (const float*)d_in[3];
    const float* bq = (const float*)d_in[4];
    const float* Wk = (const float*)d_in[5];
    const float* bk = (const float*)d_in[6];
    const float* Wv = (const float*)d_in[7];
    const float* bv = (const float*)d_in[8];
    const float* Wo = (const float*)d_in[9];
    const float* bo = (const float*)d_in[10];
    const float* gamma = (const float*)d_in[11];
    float* out = (float*)d_out;

    zero_kv_kernel<<<(BATCH * H * DK * DV + 255) / 256, 256>>>();

    dim3 gproj(D_MODEL / BN, MTOT / BM, 3);
    proj_kernel<<<gproj, 256>>>(queries, keys, values, Wq, bq, Wk, bk, Wv, bv);

    kv_kernel<<<dim3(BATCH * H, NCHUNK), 256>>>();
    fold_kernel<<<BATCH * H, 256>>>(Wo, gamma);
    qnorm_kernel<<<MTOT, 256>>>(gamma);

    dim3 gout(D_MODEL / BN, SEQ / BM, BATCH);
    out_kernel<<<gout, 256>>>(bo, out);
}

// round 5
// speedup vs baseline: 2.2593x; 2.2593x over previous
#include <cuda_runtime.h>
#include <cuda_bf16.h>
#include <cstdint>

#define DM 1024
#define H 16
#define BATCH 4
#define SEQ 8192
#define MTOT (BATCH*SEQ)

// GEMM tiling
#define BM 128
#define BN 128
#define BK 64
#define NCH (DM/BK)            // 16 K-chunks
#define LDS_ 72                // 64 + 8 pad elems -> 144B row stride
#define TILE_B (128*LDS_*2)    // 18432 B per operand tile
#define STAGE_B (4*TILE_B)     // Ah, Al, Bh, Bl = 73728 B
#define DYN (2*STAGE_B)        // 147456 B

// ---------------- scratch ----------------------------------------------------
__device__ float g_proj[3][(size_t)MTOT*DM];
__device__ __nv_bfloat16 g_inh[3][(size_t)MTOT*DM];
__device__ __nv_bfloat16 g_inl[3][(size_t)MTOT*DM];
__device__ __nv_bfloat16 g_wh[3][DM*DM];
__device__ __nv_bfloat16 g_wl[3][DM*DM];
__device__ __nv_bfloat16 g_qnh[(size_t)MTOT*DM];
__device__ __nv_bfloat16 g_qnl[(size_t)MTOT*DM];
__device__ __nv_bfloat16 g_w2h[(size_t)BATCH*DM*DM];
__device__ __nv_bfloat16 g_w2l[(size_t)BATCH*DM*DM];
__device__ float g_kv[BATCH*H*64*64];

// ---------------- helpers ------------------------------------------------------
static __device__ __forceinline__ uint32_t s2u(const void* p){
    uint32_t r;
    asm("{ .reg .u64 t; cvta.to.shared.u64 t, %1; cvt.u32.u64 %0, t; }" : "=r"(r) : "l"(p));
    return r;
}
static __device__ __forceinline__ void cp16(uint32_t dst, const void* src){
    asm volatile("cp.async.cg.shared.global [%0], [%1], 16;" :: "r"(dst), "l"(src));
}
#define CP_COMMIT() asm volatile("cp.async.commit_group;" ::: "memory")
#define LDM4(r, a) asm volatile( \
    "ldmatrix.sync.aligned.m8n8.x4.shared.b16 {%0,%1,%2,%3}, [%4];" \
    : "=r"((r)[0]),"=r"((r)[1]),"=r"((r)[2]),"=r"((r)[3]) : "r"(a))
#define MMA(d, a, b0_, b1_) asm volatile( \
    "mma.sync.aligned.m16n8k16.row.col.f32.bf16.bf16.f32 " \
    "{%0,%1,%2,%3},{%4,%5,%6,%7},{%8,%9},{%0,%1,%2,%3};" \
    : "+f"((d)[0]),"+f"((d)[1]),"+f"((d)[2]),"+f"((d)[3]) \
    : "r"((a)[0]),"r"((a)[1]),"r"((a)[2]),"r"((a)[3]), "r"(b0_),"r"(b1_))

static __device__ __forceinline__ void store_hl(__nv_bfloat16* ph, __nv_bfloat16* pl, float4 x){
    float v[4] = {x.x, x.y, x.z, x.w};
    uint32_t hw[4], lw[4];
#pragma unroll
    for (int i = 0; i < 4; i++){
        __nv_bfloat16 hb = __float2bfloat16(v[i]);
        __nv_bfloat16 lb = __float2bfloat16(v[i] - __bfloat162float(hb));
        hw[i] = __bfloat16_as_ushort(hb);
        lw[i] = __bfloat16_as_ushort(lb);
    }
    *reinterpret_cast<uint2*>(ph) = make_uint2(hw[0]|(hw[1]<<16), hw[2]|(hw[3]<<16));
    *reinterpret_cast<uint2*>(pl) = make_uint2(lw[0]|(lw[1]<<16), lw[2]|(lw[3]<<16));
}

// ---------------- mma.sync GEMM core: C = A @ B^T + bias (3-pass split) ------
static __device__ __forceinline__ void gemm_core(
    const __nv_bfloat16* __restrict__ Ah, const __nv_bfloat16* __restrict__ Al,
    const __nv_bfloat16* __restrict__ Bh, const __nv_bfloat16* __restrict__ Bl,
    const float* __restrict__ bias, float* __restrict__ C, int bm, int bn)
{
    extern __shared__ __nv_bfloat16 smbuf[];
    const uint32_t smu = s2u(smbuf);
    const int tid  = threadIdx.x;
    const int lane = tid & 31;
    const int wid  = tid >> 5;
    const int wm   = wid & 1;        // 2 warps along M (64 rows each)
    const int wn   = wid >> 1;       // 4 warps along N (32 cols each)

    float acc[4][4][4];
#pragma unroll
    for (int i = 0; i < 4; i++)
#pragma unroll
        for (int j = 0; j < 4; j++)
#pragma unroll
            for (int q = 0; q < 4; q++) acc[i][j][q] = 0.f;

    float2 bias2[4];
#pragma unroll
    for (int nt = 0; nt < 4; nt++)
        bias2[nt] = *reinterpret_cast<const float2*>(
            bias + bn + wn*32 + nt*8 + (lane & 3)*2);

    // ---- stage issue (cp.async) ----
#define ISSUE(c_) do {                                                         \
        const int c__ = (c_);                                                  \
        const uint32_t sb = smu + (uint32_t)((c__ & 1) * STAGE_B);             \
        const int k0 = c__ * BK;                                               \
        _Pragma("unroll")                                                      \
        for (int arr = 0; arr < 4; arr++){                                     \
            const __nv_bfloat16* s = (arr==0)?Ah:(arr==1)?Al:(arr==2)?Bh:Bl;   \
            const int row0 = (arr < 2) ? bm : bn;                              \
            const uint32_t ab = sb + (uint32_t)(arr * TILE_B);                 \
            _Pragma("unroll")                                                  \
            for (int it = 0; it < 4; it++){                                    \
                int id = tid + it*256;                                         \
                int r = id >> 3, cg = id & 7;                                  \
                cp16(ab + (uint32_t)(r*LDS_ + cg*8)*2,                         \
                     s + (size_t)(row0 + r)*DM + k0 + cg*8);                   \
            }                                                                  \
        }                                                                      \
        CP_COMMIT();                                                           \
    } while(0)

    ISSUE(0);
    for (int c = 0; c < NCH; c++){
        if (c + 1 < NCH){
            ISSUE(c + 1);
            asm volatile("cp.async.wait_group 1;" ::: "memory");
        } else {
            asm volatile("cp.async.wait_group 0;" ::: "memory");
        }
        __syncthreads();

        const uint32_t sb  = smu + (uint32_t)((c & 1) * STAGE_B);
#pragma unroll
        for (int ks = 0; ks < 4; ks++){
            uint32_t ah[4][4], al[4][4];
#pragma unroll
            for (int mt = 0; mt < 4; mt++){
                uint32_t ad = sb + (uint32_t)(
                    (wm*64 + mt*16 + (lane & 15))*LDS_ + ks*16 + (lane >> 4)*8)*2;
                LDM4(ah[mt], ad);
                LDM4(al[mt], ad + TILE_B);
            }
            uint32_t bh[2][4], bl[2][4];
#pragma unroll
            for (int np = 0; np < 2; np++){
                uint32_t bd = sb + (uint32_t)(2*TILE_B) + (uint32_t)(
                    (wn*32 + np*16 + (lane & 15))*LDS_ + ks*16 + (lane >> 4)*8)*2;
                LDM4(bh[np], bd);            // B stored [N][K]: non-trans gives col fragment
                LDM4(bl[np], bd + TILE_B);
            }
#pragma unroll
            for (int mt = 0; mt < 4; mt++)
#pragma unroll
                for (int nt = 0; nt < 4; nt++){
                    const int np = nt >> 1, sub = nt & 1;
                    MMA(acc[mt][nt], ah[mt], bh[np][sub], bh[np][sub+2]);
                    MMA(acc[mt][nt], ah[mt], bl[np][sub], bl[np][sub+2]);
                    MMA(acc[mt][nt], al[mt], bh[np][sub], bh[np][sub+2]);
                }
        }
        __syncthreads();
    }
#undef ISSUE

    // ---- epilogue: add bias, store fp32 ----
#pragma unroll
    for (int mt = 0; mt < 4; mt++){
        const int row = bm + wm*64 + mt*16 + (lane >> 2);
#pragma unroll
        for (int nt = 0; nt < 4; nt++){
            const int col = bn + wn*32 + nt*8 + (lane & 3)*2;
            float2 o0, o1;
            o0.x = acc[mt][nt][0] + bias2[nt].x;
            o0.y = acc[mt][nt][1] + bias2[nt].y;
            o1.x = acc[mt][nt][2] + bias2[nt].x;
            o1.y = acc[mt][nt][3] + bias2[nt].y;
            *reinterpret_cast<float2*>(C + (size_t)row*DM + col) = o0;
            *reinterpret_cast<float2*>(C + (size_t)(row+8)*DM + col) = o1;
        }
    }
}

// ---------------- GEMM wrappers ----------------------------------------------
__global__ void __launch_bounds__(256, 1) proj_mma(
    const float* __restrict__ bq, const float* __restrict__ bk, const float* __restrict__ bv)
{
    const int z = blockIdx.z;
    const float* bias = (z == 0) ? bq : (z == 1) ? bk : bv;
    gemm_core(g_inh[z], g_inl[z], g_wh[z], g_wl[z], bias, g_proj[z],
              blockIdx.y * BM, blockIdx.x * BN);
}
__global__ void __launch_bounds__(256, 1) out_mma(
    const float* __restrict__ bo, float* __restrict__ out)
{
    const int b = blockIdx.z;
    gemm_core(g_qnh + (size_t)b*SEQ*DM, g_qnl + (size_t)b*SEQ*DM,
              g_w2h + (size_t)b*DM*DM,  g_w2l + (size_t)b*DM*DM,
              bo, out + (size_t)b*SEQ*DM, blockIdx.y * BM, blockIdx.x * BN);
}

// ---------------- split kernels ----------------------------------------------
__global__ void __launch_bounds__(256) split_in(
    const float* __restrict__ q, const float* __restrict__ k, const float* __restrict__ v)
{
    int z = blockIdx.z;
    const float* s = (z == 0) ? q : (z == 1) ? k : v;
    size_t i4 = (size_t)blockIdx.x * 256 + threadIdx.x;
    float4 x = *reinterpret_cast<const float4*>(s + i4*4);
    store_hl(&g_inh[z][i4*4], &g_inl[z][i4*4], x);
}
__global__ void __launch_bounds__(256) split_w(
    const float* __restrict__ wq, const float* __restrict__ wk, const float* __restrict__ wv)
{
    int z = blockIdx.z;
    const float* s = (z == 0) ? wq : (z == 1) ? wk : wv;
    size_t i4 = (size_t)blockIdx.x * 256 + threadIdx.x;
    float4 x = *reinterpret_cast<const float4*>(s + i4*4);
    store_hl(&g_wh[z][i4*4], &g_wl[z][i4*4], x);
}

// ---------------- kv accumulation ----------------------------------------------
__global__ void zero_kv(){
    int i = blockIdx.x * 256 + threadIdx.x;
    if (i < BATCH*H*64*64) g_kv[i] = 0.f;
}
__global__ void __launch_bounds__(256) kv_kernel()
{
    const int bh = blockIdx.x, chunk = blockIdx.y;
    const int b = bh >> 4, h = bh & 15;
    const float* kbase = g_proj[1] + (size_t)b*SEQ*DM + h*64;
    const float* vbase = g_proj[2] + (size_t)b*SEQ*DM + h*64;
    __shared__ float ks[8][64], vs[8][64];
    const int tid = threadIdx.x;
    const int tj = tid & 15, ti = tid >> 4;
    float acc[4][4];
#pragma unroll
    for (int i = 0; i < 4; i++)
#pragma unroll
        for (int j = 0; j < 4; j++) acc[i][j] = 0.f;
    const int n0 = chunk * (SEQ/16);
    for (int nn = n0; nn < n0 + SEQ/16; nn += 8){
        int l = tid & 127, row = l >> 4, c = (l & 15) << 2;
        const float* src = (tid < 128) ? kbase : vbase;
        float* dst = (tid < 128) ? &ks[row][c] : &vs[row][c];
        *reinterpret_cast<float4*>(dst) =
            *reinterpret_cast<const float4*>(src + (size_t)(nn+row)*DM + c);
        __syncthreads();
#pragma unroll
        for (int r = 0; r < 8; r++){
            float kr[4], vr[4];
            *reinterpret_cast<float4*>(kr) = *reinterpret_cast<const float4*>(&ks[r][ti*4]);
            *reinterpret_cast<float4*>(vr) = *reinterpret_cast<const float4*>(&vs[r][tj*4]);
#pragma unroll
            for (int i = 0; i < 4; i++)
#pragma unroll
                for (int j = 0; j < 4; j++) acc[i][j] += kr[i] * vr[j];
        }
        __syncthreads();
    }
    float* kvp = g_kv + (size_t)bh * 4096;
#pragma unroll
    for (int i = 0; i < 4; i++)
#pragma unroll
        for (int j = 0; j < 4; j++)
            atomicAdd(&kvp[(ti*4+i)*64 + tj*4 + j], acc[i][j]);
}

// ---------------- fold: xnorm(kv) @ Wo^T -> W2T (bf16 split) -------------------
__global__ void __launch_bounds__(256) fold_kernel(
    const float* __restrict__ Wo, const float* __restrict__ gamma)
{
    const int bh = blockIdx.x, jc = blockIdx.y;
    const int b = bh >> 4, h = bh & 15;
    const int j0 = jc * 128;
    __shared__ float kvn[64][65];
    __shared__ float rn[64];
    const int tid = threadIdx.x;
    const float* kvsrc = g_kv + (size_t)bh * 4096;
    for (int l = tid; l < 4096; l += 256) kvn[l>>6][l&63] = kvsrc[l];
    __syncthreads();
    if (tid < 64){
        float s = 0.f;
#pragma unroll 16
        for (int d = 0; d < 64; d++){ float x = kvn[tid][d]; s += x*x; }
        rn[tid] = gamma[h] * rsqrtf(s);
    }
    __syncthreads();
    const int i = tid & 63, jg = tid >> 6;
    const float sc = rn[i];
    __nv_bfloat16* wh = g_w2h + (size_t)b*DM*DM;
    __nv_bfloat16* wl = g_w2l + (size_t)b*DM*DM;
    for (int j = jg; j < 128; j += 4){
        const float* wr = Wo + (size_t)(j0+j)*DM + h*64;
        float acc = 0.f;
#pragma unroll 16
        for (int d = 0; d < 64; d++) acc += kvn[i][d] * __ldg(wr + d);
        acc *= sc;
        size_t o = (size_t)(j0+j)*DM + h*64 + i;
        __nv_bfloat16 hb = __float2bfloat16(acc);
        wh[o] = hb;
        wl[o] = __float2bfloat16(acc - __bfloat162float(hb));
    }
}

// ---------------- q xnorm + split ----------------------------------------------
__global__ void __launch_bounds__(256) qnorm_kernel(const float* __restrict__ gamma)
{
    const size_t rb = (size_t)blockIdx.x * DM;
    const int t = threadIdx.x;
    float4 x = *reinterpret_cast<const float4*>(g_proj[0] + rb + t*4);
    float s = x.x*x.x + x.y*x.y + x.z*x.z + x.w*x.w;
    s += __shfl_xor_sync(0xffffffffu, s, 1);
    s += __shfl_xor_sync(0xffffffffu, s, 2);
    s += __shfl_xor_sync(0xffffffffu, s, 4);
    s += __shfl_xor_sync(0xffffffffu, s, 8);
    float sc = gamma[t >> 4] * rsqrtf(s);
    x.x *= sc; x.y *= sc; x.z *= sc; x.w *= sc;
    store_hl(g_qnh + rb + t*4, g_qnl + rb + t*4, x);
}

// ---------------- launch ----------------------------------------------------------
extern "C" void kernel_launch(void* const* d_in, const int* in_sizes, int n_in,
                              void* d_out, int out_size)
{
    const float* queries = (const float*)d_in[0];
    const float* keys    = (const float*)d_in[1];
    const float* values  = (const float*)d_in[2];
    const float* Wq = (const float*)d_in[3];
    const float* bq = (const float*)d_in[4];
    const float* Wk = (const float*)d_in[5];
    const float* bk = (const float*)d_in[6];
    const float* Wv = (const float*)d_in[7];
    const float* bv = (const float*)d_in[8];
    const float* Wo = (const float*)d_in[9];
    const float* bo = (const float*)d_in[10];
    const float* gamma = (const float*)d_in[11];
    float* out = (float*)d_out;

    cudaFuncSetAttribute(proj_mma, cudaFuncAttributeMaxDynamicSharedMemorySize, DYN);
    cudaFuncSetAttribute(out_mma,  cudaFuncAttributeMaxDynamicSharedMemorySize, DYN);

    split_in<<<dim3((MTOT*DM/4)/256, 1, 3), 256>>>(queries, keys, values);
    split_w<<<dim3((DM*DM/4)/256, 1, 3), 256>>>(Wq, Wk, Wv);
    zero_kv<<<(BATCH*H*64*64)/256, 256>>>();

    proj_mma<<<dim3(DM/BN, MTOT/BM, 3), 256, DYN>>>(bq, bk, bv);

    kv_kernel<<<dim3(BATCH*H, 16), 256>>>();
    fold_kernel<<<dim3(BATCH*H, 8), 256>>>(Wo, gamma);
    qnorm_kernel<<<MTOT, 256>>>(gamma);

    out_mma<<<dim3(DM/BN, SEQ/BM, BATCH), 256, DYN>>>(bo, out);
}

// round 6
// speedup vs baseline: 2.2996x; 1.0178x over previous
#include <cuda_runtime.h>
#include <cuda_bf16.h>
#include <cstdint>

#define DM 1024
#define H 16
#define BATCH 4
#define SEQ 8192
#define MTOT (BATCH*SEQ)

// GEMM tiling
#define BM 128
#define BN 128
#define BK 64
#define NCH (DM/BK)            // 16 K-chunks
#define LDS_ 72                // 64 + 8 pad elems -> 144B row stride
#define TILE_B (128*LDS_*2)    // 18432 B per operand tile
#define STAGE_B (4*TILE_B)     // Ah, Al, Bh, Bl = 73728 B
#define DYN (2*STAGE_B)        // 147456 B
#define NTHR 512

// ---------------- scratch ----------------------------------------------------
__device__ float g_proj[3][(size_t)MTOT*DM];
__device__ __nv_bfloat16 g_inh[3][(size_t)MTOT*DM];
__device__ __nv_bfloat16 g_inl[3][(size_t)MTOT*DM];
__device__ __nv_bfloat16 g_wh[3][DM*DM];
__device__ __nv_bfloat16 g_wl[3][DM*DM];
__device__ __nv_bfloat16 g_qnh[(size_t)MTOT*DM];
__device__ __nv_bfloat16 g_qnl[(size_t)MTOT*DM];
__device__ __nv_bfloat16 g_w2h[(size_t)BATCH*DM*DM];
__device__ __nv_bfloat16 g_w2l[(size_t)BATCH*DM*DM];
__device__ float g_kv[BATCH*H*64*64];

// ---------------- helpers ------------------------------------------------------
static __device__ __forceinline__ uint32_t s2u(const void* p){
    uint32_t r;
    asm("{ .reg .u64 t; cvta.to.shared.u64 t, %1; cvt.u32.u64 %0, t; }" : "=r"(r) : "l"(p));
    return r;
}
static __device__ __forceinline__ void cp16(uint32_t dst, const void* src){
    asm volatile("cp.async.cg.shared.global [%0], [%1], 16;" :: "r"(dst), "l"(src));
}
#define CP_COMMIT() asm volatile("cp.async.commit_group;" ::: "memory")
#define LDM4(r, a) asm volatile( \
    "ldmatrix.sync.aligned.m8n8.x4.shared.b16 {%0,%1,%2,%3}, [%4];" \
    : "=r"((r)[0]),"=r"((r)[1]),"=r"((r)[2]),"=r"((r)[3]) : "r"(a))
#define MMA(d, a, b0_, b1_) asm volatile( \
    "mma.sync.aligned.m16n8k16.row.col.f32.bf16.bf16.f32 " \
    "{%0,%1,%2,%3},{%4,%5,%6,%7},{%8,%9},{%0,%1,%2,%3};" \
    : "+f"((d)[0]),"+f"((d)[1]),"+f"((d)[2]),"+f"((d)[3]) \
    : "r"((a)[0]),"r"((a)[1]),"r"((a)[2]),"r"((a)[3]), "r"(b0_),"r"(b1_))

static __device__ __forceinline__ void store_hl(__nv_bfloat16* ph, __nv_bfloat16* pl, float4 x){
    float v[4] = {x.x, x.y, x.z, x.w};
    uint32_t hw[4], lw[4];
#pragma unroll
    for (int i = 0; i < 4; i++){
        __nv_bfloat16 hb = __float2bfloat16(v[i]);
        __nv_bfloat16 lb = __float2bfloat16(v[i] - __bfloat162float(hb));
        hw[i] = __bfloat16_as_ushort(hb);
        lw[i] = __bfloat16_as_ushort(lb);
    }
    *reinterpret_cast<uint2*>(ph) = make_uint2(hw[0]|(hw[1]<<16), hw[2]|(hw[3]<<16));
    *reinterpret_cast<uint2*>(pl) = make_uint2(lw[0]|(lw[1]<<16), lw[2]|(lw[3]<<16));
}

// ---------------- mma.sync GEMM core: C = A @ B^T + bias (3-pass split) ------
// 512 threads: warp grid 4(M) x 4(N), each warp 32x32 output tile.
static __device__ __forceinline__ void gemm_core(
    const __nv_bfloat16* __restrict__ Ah, const __nv_bfloat16* __restrict__ Al,
    const __nv_bfloat16* __restrict__ Bh, const __nv_bfloat16* __restrict__ Bl,
    const float* __restrict__ bias, float* __restrict__ C, int bm, int bn)
{
    extern __shared__ __nv_bfloat16 smbuf[];
    const uint32_t smu = s2u(smbuf);
    const int tid  = threadIdx.x;
    const int lane = tid & 31;
    const int wid  = tid >> 5;
    const int wm   = wid & 3;        // 4 warps along M (32 rows each)
    const int wn   = wid >> 2;       // 4 warps along N (32 cols each)

    float acc[2][4][4];
#pragma unroll
    for (int i = 0; i < 2; i++)
#pragma unroll
        for (int j = 0; j < 4; j++)
#pragma unroll
            for (int q = 0; q < 4; q++) acc[i][j][q] = 0.f;

    float2 bias2[4];
#pragma unroll
    for (int nt = 0; nt < 4; nt++)
        bias2[nt] = *reinterpret_cast<const float2*>(
            bias + bn + wn*32 + nt*8 + (lane & 3)*2);

    // ---- stage issue (cp.async): 4 arrays x 1024 cp16 / 512 thr = 8 per thread
#define ISSUE(c_) do {                                                         \
        const int c__ = (c_);                                                  \
        const uint32_t sb = smu + (uint32_t)((c__ & 1) * STAGE_B);             \
        const int k0 = c__ * BK;                                               \
        _Pragma("unroll")                                                      \
        for (int arr = 0; arr < 4; arr++){                                     \
            const __nv_bfloat16* s = (arr==0)?Ah:(arr==1)?Al:(arr==2)?Bh:Bl;   \
            const int row0 = (arr < 2) ? bm : bn;                              \
            const uint32_t ab = sb + (uint32_t)(arr * TILE_B);                 \
            _Pragma("unroll")                                                  \
            for (int it = 0; it < 2; it++){                                    \
                int id = tid + it*NTHR;                                        \
                int r = id >> 3, cg = id & 7;                                  \
                cp16(ab + (uint32_t)(r*LDS_ + cg*8)*2,                         \
                     s + (size_t)(row0 + r)*DM + k0 + cg*8);                   \
            }                                                                  \
        }                                                                      \
        CP_COMMIT();                                                           \
    } while(0)

    ISSUE(0);
    for (int c = 0; c < NCH; c++){
        if (c + 1 < NCH){
            ISSUE(c + 1);
            asm volatile("cp.async.wait_group 1;" ::: "memory");
        } else {
            asm volatile("cp.async.wait_group 0;" ::: "memory");
        }
        __syncthreads();

        const uint32_t sb  = smu + (uint32_t)((c & 1) * STAGE_B);
#pragma unroll
        for (int ks = 0; ks < 4; ks++){
            uint32_t ah[2][4], al[2][4];
#pragma unroll
            for (int mt = 0; mt < 2; mt++){
                uint32_t ad = sb + (uint32_t)(
                    (wm*32 + mt*16 + (lane & 15))*LDS_ + ks*16 + (lane >> 4)*8)*2;
                LDM4(ah[mt], ad);
                LDM4(al[mt], ad + TILE_B);
            }
            uint32_t bh[2][4], bl[2][4];
#pragma unroll
            for (int np = 0; np < 2; np++){
                uint32_t bd = sb + (uint32_t)(2*TILE_B) + (uint32_t)(
                    (wn*32 + np*16 + (lane & 15))*LDS_ + ks*16 + (lane >> 4)*8)*2;
                LDM4(bh[np], bd);            // B stored [N][K]: non-trans = col fragment
                LDM4(bl[np], bd + TILE_B);
            }
#pragma unroll
            for (int mt = 0; mt < 2; mt++)
#pragma unroll
                for (int nt = 0; nt < 4; nt++){
                    const int np = nt >> 1, sub = nt & 1;
                    MMA(acc[mt][nt], ah[mt], bh[np][sub], bh[np][sub+2]);
                    MMA(acc[mt][nt], ah[mt], bl[np][sub], bl[np][sub+2]);
                    MMA(acc[mt][nt], al[mt], bh[np][sub], bh[np][sub+2]);
                }
        }
        __syncthreads();
    }
#undef ISSUE

    // ---- epilogue: add bias, store fp32 ----
#pragma unroll
    for (int mt = 0; mt < 2; mt++){
        const int row = bm + wm*32 + mt*16 + (lane >> 2);
#pragma unroll
        for (int nt = 0; nt < 4; nt++){
            const int col = bn + wn*32 + nt*8 + (lane & 3)*2;
            float2 o0, o1;
            o0.x = acc[mt][nt][0] + bias2[nt].x;
            o0.y = acc[mt][nt][1] + bias2[nt].y;
            o1.x = acc[mt][nt][2] + bias2[nt].x;
            o1.y = acc[mt][nt][3] + bias2[nt].y;
            *reinterpret_cast<float2*>(C + (size_t)row*DM + col) = o0;
            *reinterpret_cast<float2*>(C + (size_t)(row+8)*DM + col) = o1;
        }
    }
}

// ---------------- GEMM wrappers ----------------------------------------------
__global__ void __launch_bounds__(NTHR, 1) proj_mma(
    const float* __restrict__ bq, const float* __restrict__ bk, const float* __restrict__ bv)
{
    const int z = blockIdx.z;
    const float* bias = (z == 0) ? bq : (z == 1) ? bk : bv;
    gemm_core(g_inh[z], g_inl[z], g_wh[z], g_wl[z], bias, g_proj[z],
              blockIdx.y * BM, blockIdx.x * BN);
}
__global__ void __launch_bounds__(NTHR, 1) out_mma(
    const float* __restrict__ bo, float* __restrict__ out)
{
    const int b = blockIdx.z;
    gemm_core(g_qnh + (size_t)b*SEQ*DM, g_qnl + (size_t)b*SEQ*DM,
              g_w2h + (size_t)b*DM*DM,  g_w2l + (size_t)b*DM*DM,
              bo, out + (size_t)b*SEQ*DM, blockIdx.y * BM, blockIdx.x * BN);
}

// ---------------- split kernels ----------------------------------------------
__global__ void __launch_bounds__(256) split_in(
    const float* __restrict__ q, const float* __restrict__ k, const float* __restrict__ v)
{
    int z = blockIdx.z;
    const float* s = (z == 0) ? q : (z == 1) ? k : v;
    size_t i4 = (size_t)blockIdx.x * 256 + threadIdx.x;
    float4 x = *reinterpret_cast<const float4*>(s + i4*4);
    store_hl(&g_inh[z][i4*4], &g_inl[z][i4*4], x);
}
__global__ void __launch_bounds__(256) split_w(
    const float* __restrict__ wq, const float* __restrict__ wk, const float* __restrict__ wv)
{
    int z = blockIdx.z;
    const float* s = (z == 0) ? wq : (z == 1) ? wk : wv;
    size_t i4 = (size_t)blockIdx.x * 256 + threadIdx.x;
    float4 x = *reinterpret_cast<const float4*>(s + i4*4);
    store_hl(&g_wh[z][i4*4], &g_wl[z][i4*4], x);
}

// ---------------- kv accumulation ----------------------------------------------
__global__ void zero_kv(){
    int i = blockIdx.x * 256 + threadIdx.x;
    if (i < BATCH*H*64*64) g_kv[i] = 0.f;
}
__global__ void __launch_bounds__(256) kv_kernel()
{
    const int bh = blockIdx.x, chunk = blockIdx.y;
    const int b = bh >> 4, h = bh & 15;
    const float* kbase = g_proj[1] + (size_t)b*SEQ*DM + h*64;
    const float* vbase = g_proj[2] + (size_t)b*SEQ*DM + h*64;
    __shared__ float ks[8][64], vs[8][64];
    const int tid = threadIdx.x;
    const int tj = tid & 15, ti = tid >> 4;
    float acc[4][4];
#pragma unroll
    for (int i = 0; i < 4; i++)
#pragma unroll
        for (int j = 0; j < 4; j++) acc[i][j] = 0.f;
    const int n0 = chunk * (SEQ/16);
    for (int nn = n0; nn < n0 + SEQ/16; nn += 8){
        int l = tid & 127, row = l >> 4, c = (l & 15) << 2;
        const float* src = (tid < 128) ? kbase : vbase;
        float* dst = (tid < 128) ? &ks[row][c] : &vs[row][c];
        *reinterpret_cast<float4*>(dst) =
            *reinterpret_cast<const float4*>(src + (size_t)(nn+row)*DM + c);
        __syncthreads();
#pragma unroll
        for (int r = 0; r < 8; r++){
            float kr[4], vr[4];
            *reinterpret_cast<float4*>(kr) = *reinterpret_cast<const float4*>(&ks[r][ti*4]);
            *reinterpret_cast<float4*>(vr) = *reinterpret_cast<const float4*>(&vs[r][tj*4]);
#pragma unroll
            for (int i = 0; i < 4; i++)
#pragma unroll
                for (int j = 0; j < 4; j++) acc[i][j] += kr[i] * vr[j];
        }
        __syncthreads();
    }
    float* kvp = g_kv + (size_t)bh * 4096;
#pragma unroll
    for (int i = 0; i < 4; i++)
#pragma unroll
        for (int j = 0; j < 4; j++)
            atomicAdd(&kvp[(ti*4+i)*64 + tj*4 + j], acc[i][j]);
}

// ---------------- fold: xnorm(kv) @ Wo^T -> W2T (bf16 split) -------------------
__global__ void __launch_bounds__(256) fold_kernel(
    const float* __restrict__ Wo, const float* __restrict__ gamma)
{
    const int bh = blockIdx.x, jc = blockIdx.y;
    const int b = bh >> 4, h = bh & 15;
    const int j0 = jc * 128;
    __shared__ float kvn[64][65];
    __shared__ float rn[64];
    const int tid = threadIdx.x;
    const float* kvsrc = g_kv + (size_t)bh * 4096;
    for (int l = tid; l < 4096; l += 256) kvn[l>>6][l&63] = kvsrc[l];
    __syncthreads();
    if (tid < 64){
        float s = 0.f;
#pragma unroll 16
        for (int d = 0; d < 64; d++){ float x = kvn[tid][d]; s += x*x; }
        rn[tid] = gamma[h] * rsqrtf(s);
    }
    __syncthreads();
    const int i = tid & 63, jg = tid >> 6;
    const float sc = rn[i];
    __nv_bfloat16* wh = g_w2h + (size_t)b*DM*DM;
    __nv_bfloat16* wl = g_w2l + (size_t)b*DM*DM;
    for (int j = jg; j < 128; j += 4){
        const float* wr = Wo + (size_t)(j0+j)*DM + h*64;
        float acc = 0.f;
#pragma unroll 16
        for (int d = 0; d < 64; d++) acc += kvn[i][d] * __ldg(wr + d);
        acc *= sc;
        size_t o = (size_t)(j0+j)*DM + h*64 + i;
        __nv_bfloat16 hb = __float2bfloat16(acc);
        wh[o] = hb;
        wl[o] = __float2bfloat16(acc - __bfloat162float(hb));
    }
}

// ---------------- q xnorm + split ----------------------------------------------
__global__ void __launch_bounds__(256) qnorm_kernel(const float* __restrict__ gamma)
{
    const size_t rb = (size_t)blockIdx.x * DM;
    const int t = threadIdx.x;
    float4 x = *reinterpret_cast<const float4*>(g_proj[0] + rb + t*4);
    float s = x.x*x.x + x.y*x.y + x.z*x.z + x.w*x.w;
    s += __shfl_xor_sync(0xffffffffu, s, 1);
    s += __shfl_xor_sync(0xffffffffu, s, 2);
    s += __shfl_xor_sync(0xffffffffu, s, 4);
    s += __shfl_xor_sync(0xffffffffu, s, 8);
    float sc = gamma[t >> 4] * rsqrtf(s);
    x.x *= sc; x.y *= sc; x.z *= sc; x.w *= sc;
    store_hl(g_qnh + rb + t*4, g_qnl + rb + t*4, x);
}

// ---------------- launch ----------------------------------------------------------
extern "C" void kernel_launch(void* const* d_in, const int* in_sizes, int n_in,
                              void* d_out, int out_size)
{
    const float* queries = (const float*)d_in[0];
    const float* keys    = (const float*)d_in[1];
    const float* values  = (const float*)d_in[2];
    const float* Wq = (const float*)d_in[3];
    const float* bq = (const float*)d_in[4];
    const float* Wk = (const float*)d_in[5];
    const float* bk = (const float*)d_in[6];
    const float* Wv = (const float*)d_in[7];
    const float* bv = (const float*)d_in[8];
    const float* Wo = (const float*)d_in[9];
    const float* bo = (const float*)d_in[10];
    const float* gamma = (const float*)d_in[11];
    float* out = (float*)d_out;

    cudaFuncSetAttribute(proj_mma, cudaFuncAttributeMaxDynamicSharedMemorySize, DYN);
    cudaFuncSetAttribute(out_mma,  cudaFuncAttributeMaxDynamicSharedMemorySize, DYN);

    split_in<<<dim3((MTOT*DM/4)/256, 1, 3), 256>>>(queries, keys, values);
    split_w<<<dim3((DM*DM/4)/256, 1, 3), 256>>>(Wq, Wk, Wv);
    zero_kv<<<(BATCH*H*64*64)/256, 256>>>();

    proj_mma<<<dim3(DM/BN, MTOT/BM, 3), NTHR, DYN>>>(bq, bk, bv);

    kv_kernel<<<dim3(BATCH*H, 16), 256>>>();
    fold_kernel<<<dim3(BATCH*H, 8), 256>>>(Wo, gamma);
    qnorm_kernel<<<MTOT, 256>>>(gamma);

    out_mma<<<dim3(DM/BN, SEQ/BM, BATCH), NTHR, DYN>>>(bo, out);
}

// round 7
// speedup vs baseline: 2.3792x; 1.0346x over previous
#include <cuda_runtime.h>
#include <cuda_bf16.h>
#include <cstdint>

#define DM 1024
#define H 16
#define BATCH 4
#define SEQ 8192
#define MTOT (BATCH*SEQ)

// GEMM tiling: CTA 128x256, warp 64x64 (2M x 4N warps, 256 threads)
#define BM 128
#define BN 256
#define BK 64
#define NCH (DM/BK)             // 16 K-chunks
#define LDS_ 72                 // 64 + 8 pad elems -> 144B row stride
#define A_TB (128*LDS_*2)       // 18432 B per A operand tile
#define B_TB (256*LDS_*2)       // 36864 B per B operand tile
#define STAGE_B (2*A_TB+2*B_TB) // 110592 B (Ah, Al, Bh, Bl)
#define DYN (2*STAGE_B)         // 221184 B
#define NTHR 256

// ---------------- scratch ----------------------------------------------------
__device__ float g_proj[3][(size_t)MTOT*DM];
__device__ __nv_bfloat16 g_inh[3][(size_t)MTOT*DM];
__device__ __nv_bfloat16 g_inl[3][(size_t)MTOT*DM];
__device__ __nv_bfloat16 g_wh[3][DM*DM];
__device__ __nv_bfloat16 g_wl[3][DM*DM];
__device__ __nv_bfloat16 g_qnh[(size_t)MTOT*DM];
__device__ __nv_bfloat16 g_qnl[(size_t)MTOT*DM];
__device__ __nv_bfloat16 g_w2h[(size_t)BATCH*DM*DM];
__device__ __nv_bfloat16 g_w2l[(size_t)BATCH*DM*DM];
__device__ float g_kv[BATCH*H*64*64];

// ---------------- helpers ------------------------------------------------------
static __device__ __forceinline__ uint32_t s2u(const void* p){
    uint32_t r;
    asm("{ .reg .u64 t; cvta.to.shared.u64 t, %1; cvt.u32.u64 %0, t; }" : "=r"(r) : "l"(p));
    return r;
}
static __device__ __forceinline__ void cp16(uint32_t dst, const void* src){
    asm volatile("cp.async.cg.shared.global [%0], [%1], 16;" :: "r"(dst), "l"(src));
}
#define CP_COMMIT() asm volatile("cp.async.commit_group;" ::: "memory")
#define LDM4(r, a) asm volatile( \
    "ldmatrix.sync.aligned.m8n8.x4.shared.b16 {%0,%1,%2,%3}, [%4];" \
    : "=r"((r)[0]),"=r"((r)[1]),"=r"((r)[2]),"=r"((r)[3]) : "r"(a))
#define MMA(d, a, b0_, b1_) asm volatile( \
    "mma.sync.aligned.m16n8k16.row.col.f32.bf16.bf16.f32 " \
    "{%0,%1,%2,%3},{%4,%5,%6,%7},{%8,%9},{%0,%1,%2,%3};" \
    : "+f"((d)[0]),"+f"((d)[1]),"+f"((d)[2]),"+f"((d)[3]) \
    : "r"((a)[0]),"r"((a)[1]),"r"((a)[2]),"r"((a)[3]), "r"(b0_),"r"(b1_))

static __device__ __forceinline__ void store_hl(__nv_bfloat16* ph, __nv_bfloat16* pl, float4 x){
    float v[4] = {x.x, x.y, x.z, x.w};
    uint32_t hw[4], lw[4];
#pragma unroll
    for (int i = 0; i < 4; i++){
        __nv_bfloat16 hb = __float2bfloat16(v[i]);
        __nv_bfloat16 lb = __float2bfloat16(v[i] - __bfloat162float(hb));
        hw[i] = __bfloat16_as_ushort(hb);
        lw[i] = __bfloat16_as_ushort(lb);
    }
    *reinterpret_cast<uint2*>(ph) = make_uint2(hw[0]|(hw[1]<<16), hw[2]|(hw[3]<<16));
    *reinterpret_cast<uint2*>(pl) = make_uint2(lw[0]|(lw[1]<<16), lw[2]|(lw[3]<<16));
}

// ---------------- mma.sync GEMM core: C = A @ B^T + bias (3-pass split) ------
// 256 threads, warp grid 2(M) x 4(N), warp tile 64x64.
static __device__ __forceinline__ void gemm_core(
    const __nv_bfloat16* __restrict__ Ah, const __nv_bfloat16* __restrict__ Al,
    const __nv_bfloat16* __restrict__ Bh, const __nv_bfloat16* __restrict__ Bl,
    const float* __restrict__ bias, float* __restrict__ C, int bm, int bn)
{
    extern __shared__ __nv_bfloat16 smbuf[];
    const uint32_t smu = s2u(smbuf);
    const int tid  = threadIdx.x;
    const int lane = tid & 31;
    const int wid  = tid >> 5;
    const int wm   = wid & 1;        // 2 warps along M (64 rows each)
    const int wn   = wid >> 1;       // 4 warps along N (64 cols each)

    float acc[4][8][4];
#pragma unroll
    for (int i = 0; i < 4; i++)
#pragma unroll
        for (int j = 0; j < 8; j++)
#pragma unroll
            for (int q = 0; q < 4; q++) acc[i][j][q] = 0.f;

    // ---- stage issue (cp.async): Ah/Al 1024 cp16 each, Bh/Bl 2048 each ----
#define ISSUE(c_) do {                                                         \
        const int c__ = (c_);                                                  \
        const uint32_t sb = smu + (uint32_t)((c__ & 1) * STAGE_B);             \
        const int k0 = c__ * BK;                                               \
        _Pragma("unroll")                                                      \
        for (int arr = 0; arr < 4; arr++){                                     \
            const __nv_bfloat16* s = (arr==0)?Ah:(arr==1)?Al:(arr==2)?Bh:Bl;   \
            const int row0 = (arr < 2) ? bm : bn;                              \
            const int nit  = (arr < 2) ? 4 : 8;                                \
            const uint32_t ab = sb + (uint32_t)((arr==0)?0:(arr==1)?A_TB:      \
                                     (arr==2)?2*A_TB:(2*A_TB+B_TB));           \
            _Pragma("unroll")                                                  \
            for (int it = 0; it < nit; it++){                                  \
                int id = tid + it*NTHR;                                        \
                int r = id >> 3, cg = id & 7;                                  \
                cp16(ab + (uint32_t)(r*LDS_ + cg*8)*2,                         \
                     s + (size_t)(row0 + r)*DM + k0 + cg*8);                   \
            }                                                                  \
        }                                                                      \
        CP_COMMIT();                                                           \
    } while(0)

    ISSUE(0);
    for (int c = 0; c < NCH; c++){
        if (c + 1 < NCH){
            ISSUE(c + 1);
            asm volatile("cp.async.wait_group 1;" ::: "memory");
        } else {
            asm volatile("cp.async.wait_group 0;" ::: "memory");
        }
        __syncthreads();

        const uint32_t sb  = smu + (uint32_t)((c & 1) * STAGE_B);
#pragma unroll
        for (int ks = 0; ks < 4; ks++){
            // B fragments for 64 cols: 4 n16 blocks, hi+lo
            uint32_t bh[4][4], bl[4][4];
#pragma unroll
            for (int np = 0; np < 4; np++){
                uint32_t bd = sb + (uint32_t)(2*A_TB) + (uint32_t)(
                    (wn*64 + np*16 + (lane & 15))*LDS_ + ks*16 + (lane >> 4)*8)*2;
                LDM4(bh[np], bd);            // B stored [N][K]: non-trans = col fragment
                LDM4(bl[np], bd + B_TB);
            }
            // Stream A fragments per 16-row tile
#pragma unroll
            for (int mt = 0; mt < 4; mt++){
                uint32_t ah[4], al[4];
                uint32_t ad = sb + (uint32_t)(
                    (wm*64 + mt*16 + (lane & 15))*LDS_ + ks*16 + (lane >> 4)*8)*2;
                LDM4(ah, ad);
                LDM4(al, ad + A_TB);
#pragma unroll
                for (int nt = 0; nt < 8; nt++){
                    const int np = nt >> 1, sub = nt & 1;
                    MMA(acc[mt][nt], ah, bh[np][sub], bh[np][sub+2]);
                    MMA(acc[mt][nt], ah, bl[np][sub], bl[np][sub+2]);
                    MMA(acc[mt][nt], al, bh[np][sub], bh[np][sub+2]);
                }
            }
        }
        __syncthreads();
    }
#undef ISSUE

    // ---- epilogue: add bias, store fp32 ----
#pragma unroll
    for (int mt = 0; mt < 4; mt++){
        const int row = bm + wm*64 + mt*16 + (lane >> 2);
#pragma unroll
        for (int nt = 0; nt < 8; nt++){
            const int col = bn + wn*64 + nt*8 + (lane & 3)*2;
            const float bx = bias[col], by = bias[col+1];
            float2 o0, o1;
            o0.x = acc[mt][nt][0] + bx;
            o0.y = acc[mt][nt][1] + by;
            o1.x = acc[mt][nt][2] + bx;
            o1.y = acc[mt][nt][3] + by;
            *reinterpret_cast<float2*>(C + (size_t)row*DM + col) = o0;
            *reinterpret_cast<float2*>(C + (size_t)(row+8)*DM + col) = o1;
        }
    }
}

// ---------------- GEMM wrappers ----------------------------------------------
__global__ void __launch_bounds__(NTHR, 1) proj_mma(
    const float* __restrict__ bq, const float* __restrict__ bk, const float* __restrict__ bv)
{
    const int z = blockIdx.z;
    const float* bias = (z == 0) ? bq : (z == 1) ? bk : bv;
    gemm_core(g_inh[z], g_inl[z], g_wh[z], g_wl[z], bias, g_proj[z],
              blockIdx.y * BM, blockIdx.x * BN);
}
__global__ void __launch_bounds__(NTHR, 1) out_mma(
    const float* __restrict__ bo, float* __restrict__ out)
{
    const int b = blockIdx.z;
    gemm_core(g_qnh + (size_t)b*SEQ*DM, g_qnl + (size_t)b*SEQ*DM,
              g_w2h + (size_t)b*DM*DM,  g_w2l + (size_t)b*DM*DM,
              bo, out + (size_t)b*SEQ*DM, blockIdx.y * BM, blockIdx.x * BN);
}

// ---------------- split kernels ----------------------------------------------
__global__ void __launch_bounds__(256) split_in(
    const float* __restrict__ q, const float* __restrict__ k, const float* __restrict__ v)
{
    int z = blockIdx.z;
    const float* s = (z == 0) ? q : (z == 1) ? k : v;
    size_t i4 = (size_t)blockIdx.x * 256 + threadIdx.x;
    float4 x = *reinterpret_cast<const float4*>(s + i4*4);
    store_hl(&g_inh[z][i4*4], &g_inl[z][i4*4], x);
}
__global__ void __launch_bounds__(256) split_w(
    const float* __restrict__ wq, const float* __restrict__ wk, const float* __restrict__ wv)
{
    int z = blockIdx.z;
    const float* s = (z == 0) ? wq : (z == 1) ? wk : wv;
    size_t i4 = (size_t)blockIdx.x * 256 + threadIdx.x;
    float4 x = *reinterpret_cast<const float4*>(s + i4*4);
    store_hl(&g_wh[z][i4*4], &g_wl[z][i4*4], x);
}

// ---------------- kv accumulation ----------------------------------------------
__global__ void zero_kv(){
    int i = blockIdx.x * 256 + threadIdx.x;
    if (i < BATCH*H*64*64) g_kv[i] = 0.f;
}
__global__ void __launch_bounds__(256) kv_kernel()
{
    const int bh = blockIdx.x, chunk = blockIdx.y;
    const int b = bh >> 4, h = bh & 15;
    const float* kbase = g_proj[1] + (size_t)b*SEQ*DM + h*64;
    const float* vbase = g_proj[2] + (size_t)b*SEQ*DM + h*64;
    __shared__ float ks[8][64], vs[8][64];
    const int tid = threadIdx.x;
    const int tj = tid & 15, ti = tid >> 4;
    float acc[4][4];
#pragma unroll
    for (int i = 0; i < 4; i++)
#pragma unroll
        for (int j = 0; j < 4; j++) acc[i][j] = 0.f;
    const int n0 = chunk * (SEQ/16);
    for (int nn = n0; nn < n0 + SEQ/16; nn += 8){
        int l = tid & 127, row = l >> 4, c = (l & 15) << 2;
        const float* src = (tid < 128) ? kbase : vbase;
        float* dst = (tid < 128) ? &ks[row][c] : &vs[row][c];
        *reinterpret_cast<float4*>(dst) =
            *reinterpret_cast<const float4*>(src + (size_t)(nn+row)*DM + c);
        __syncthreads();
#pragma unroll
        for (int r = 0; r < 8; r++){
            float kr[4], vr[4];
            *reinterpret_cast<float4*>(kr) = *reinterpret_cast<const float4*>(&ks[r][ti*4]);
            *reinterpret_cast<float4*>(vr) = *reinterpret_cast<const float4*>(&vs[r][tj*4]);
#pragma unroll
            for (int i = 0; i < 4; i++)
#pragma unroll
                for (int j = 0; j < 4; j++) acc[i][j] += kr[i] * vr[j];
        }
        __syncthreads();
    }
    float* kvp = g_kv + (size_t)bh * 4096;
#pragma unroll
    for (int i = 0; i < 4; i++)
#pragma unroll
        for (int j = 0; j < 4; j++)
            atomicAdd(&kvp[(ti*4+i)*64 + tj*4 + j], acc[i][j]);
}

// ---------------- fold: xnorm(kv) @ Wo^T -> W2T (bf16 split) -------------------
__global__ void __launch_bounds__(256) fold_kernel(
    const float* __restrict__ Wo, const float* __restrict__ gamma)
{
    const int bh = blockIdx.x, jc = blockIdx.y;
    const int b = bh >> 4, h = bh & 15;
    const int j0 = jc * 128;
    __shared__ float kvn[64][65];
    __shared__ float rn[64];
    const int tid = threadIdx.x;
    const float* kvsrc = g_kv + (size_t)bh * 4096;
    for (int l = tid; l < 4096; l += 256) kvn[l>>6][l&63] = kvsrc[l];
    __syncthreads();
    if (tid < 64){
        float s = 0.f;
#pragma unroll 16
        for (int d = 0; d < 64; d++){ float x = kvn[tid][d]; s += x*x; }
        rn[tid] = gamma[h] * rsqrtf(s);
    }
    __syncthreads();
    const int i = tid & 63, jg = tid >> 6;
    const float sc = rn[i];
    __nv_bfloat16* wh = g_w2h + (size_t)b*DM*DM;
    __nv_bfloat16* wl = g_w2l + (size_t)b*DM*DM;
    for (int j = jg; j < 128; j += 4){
        const float* wr = Wo + (size_t)(j0+j)*DM + h*64;
        float acc = 0.f;
#pragma unroll 16
        for (int d = 0; d < 64; d++) acc += kvn[i][d] * __ldg(wr + d);
        acc *= sc;
        size_t o = (size_t)(j0+j)*DM + h*64 + i;
        __nv_bfloat16 hb = __float2bfloat16(acc);
        wh[o] = hb;
        wl[o] = __float2bfloat16(acc - __bfloat162float(hb));
    }
}

// ---------------- q xnorm + split ----------------------------------------------
__global__ void __launch_bounds__(256) qnorm_kernel(const float* __restrict__ gamma)
{
    const size_t rb = (size_t)blockIdx.x * DM;
    const int t = threadIdx.x;
    float4 x = *reinterpret_cast<const float4*>(g_proj[0] + rb + t*4);
    float s = x.x*x.x + x.y*x.y + x.z*x.z + x.w*x.w;
    s += __shfl_xor_sync(0xffffffffu, s, 1);
    s += __shfl_xor_sync(0xffffffffu, s, 2);
    s += __shfl_xor_sync(0xffffffffu, s, 4);
    s += __shfl_xor_sync(0xffffffffu, s, 8);
    float sc = gamma[t >> 4] * rsqrtf(s);
    x.x *= sc; x.y *= sc; x.z *= sc; x.w *= sc;
    store_hl(g_qnh + rb + t*4, g_qnl + rb + t*4, x);
}

// ---------------- launch ----------------------------------------------------------
extern "C" void kernel_launch(void* const* d_in, const int* in_sizes, int n_in,
                              void* d_out, int out_size)
{
    const float* queries = (const float*)d_in[0];
    const float* keys    = (const float*)d_in[1];
    const float* values  = (const float*)d_in[2];
    const float* Wq = (const float*)d_in[3];
    const float* bq = (const float*)d_in[4];
    const float* Wk = (const float*)d_in[5];
    const float* bk = (const float*)d_in[6];
    const float* Wv = (const float*)d_in[7];
    const float* bv = (const float*)d_in[8];
    const float* Wo = (const float*)d_in[9];
    const float* bo = (const float*)d_in[10];
    const float* gamma = (const float*)d_in[11];
    float* out = (float*)d_out;

    cudaFuncSetAttribute(proj_mma, cudaFuncAttributeMaxDynamicSharedMemorySize, DYN);
    cudaFuncSetAttribute(out_mma,  cudaFuncAttributeMaxDynamicSharedMemorySize, DYN);

    split_in<<<dim3((MTOT*DM/4)/256, 1, 3), 256>>>(queries, keys, values);
    split_w<<<dim3((DM*DM/4)/256, 1, 3), 256>>>(Wq, Wk, Wv);
    zero_kv<<<(BATCH*H*64*64)/256, 256>>>();

    proj_mma<<<dim3(DM/BN, MTOT/BM, 3), NTHR, DYN>>>(bq, bk, bv);

    kv_kernel<<<dim3(BATCH*H, 16), 256>>>();
    fold_kernel<<<dim3(BATCH*H, 8), 256>>>(Wo, gamma);
    qnorm_kernel<<<MTOT, 256>>>(gamma);

    out_mma<<<dim3(DM/BN, SEQ/BM, BATCH), NTHR, DYN>>>(bo, out);
}

// round 8
// speedup vs baseline: 3.3571x; 1.4110x over previous
#include <cuda_runtime.h>
#include <cuda_fp16.h>
#include <cstdint>

#define DM 1024
#define H 16
#define BATCH 4
#define SEQ 8192
#define MTOT (BATCH*SEQ)

// GEMM tiling: CTA 128x256, warp 64x64 (2M x 4N warps, 256 threads)
#define BM 128
#define BN 256
#define BK 64
#define NCH (DM/BK)             // 16 K-chunks
#define LDS_ 72                 // 64 + 8 pad elems -> 144B row stride
#define A_TB (128*LDS_*2)       // 18432 B per A tile
#define B_TB (256*LDS_*2)       // 36864 B per B tile
#define STAGE_B (2*A_TB+B_TB)   // 73728 B (Ah, Al, Bh)
#define NSTG 3
#define DYN (NSTG*STAGE_B)      // 221184 B
#define NTHR 256

// ---------------- scratch ----------------------------------------------------
__device__ float g_kvin[2][(size_t)MTOT*DM];                  // k, v fp32
__device__ __half g_inh[3][(size_t)MTOT*DM];
__device__ __half g_inl[3][(size_t)MTOT*DM];
__device__ __half g_w[3][DM*DM];
__device__ __half g_qnh[(size_t)MTOT*DM];
__device__ __half g_qnl[(size_t)MTOT*DM];
__device__ __half g_w2[(size_t)BATCH*DM*DM];
__device__ float g_kv[BATCH*H*64*64];

// ---------------- helpers ------------------------------------------------------
static __device__ __forceinline__ uint32_t s2u(const void* p){
    uint32_t r;
    asm("{ .reg .u64 t; cvta.to.shared.u64 t, %1; cvt.u32.u64 %0, t; }" : "=r"(r) : "l"(p));
    return r;
}
static __device__ __forceinline__ void cp16(uint32_t dst, const void* src){
    asm volatile("cp.async.cg.shared.global [%0], [%1], 16;" :: "r"(dst), "l"(src));
}
#define CP_COMMIT() asm volatile("cp.async.commit_group;" ::: "memory")
#define LDM4(r, a) asm volatile( \
    "ldmatrix.sync.aligned.m8n8.x4.shared.b16 {%0,%1,%2,%3}, [%4];" \
    : "=r"((r)[0]),"=r"((r)[1]),"=r"((r)[2]),"=r"((r)[3]) : "r"(a))
#define MMA(d, a, b0_, b1_) asm volatile( \
    "mma.sync.aligned.m16n8k16.row.col.f32.f16.f16.f32 " \
    "{%0,%1,%2,%3},{%4,%5,%6,%7},{%8,%9},{%0,%1,%2,%3};" \
    : "+f"((d)[0]),"+f"((d)[1]),"+f"((d)[2]),"+f"((d)[3]) \
    : "r"((a)[0]),"r"((a)[1]),"r"((a)[2]),"r"((a)[3]), "r"(b0_),"r"(b1_))

static __device__ __forceinline__ void store_hl(__half* ph, __half* pl, float4 x){
    float v[4] = {x.x, x.y, x.z, x.w};
    uint32_t hw[4], lw[4];
#pragma unroll
    for (int i = 0; i < 4; i++){
        __half hb = __float2half(v[i]);
        __half lb = __float2half(v[i] - __half2float(hb));
        hw[i] = __half_as_ushort(hb);
        lw[i] = __half_as_ushort(lb);
    }
    *reinterpret_cast<uint2*>(ph) = make_uint2(hw[0]|(hw[1]<<16), hw[2]|(hw[3]<<16));
    *reinterpret_cast<uint2*>(pl) = make_uint2(lw[0]|(lw[1]<<16), lw[2]|(lw[3]<<16));
}

// ---------------- fp16 2-pass GEMM core: C = (Ah+Al) @ Bh^T + bias ------------
// EPI 0: bias + fp32 store to C.  EPI 1: bias + per-head xnorm + fp16 hi/lo store.
// EPI 2: like 0 but also fp16 hi/lo NOT needed; unused.
template<int EPI>
static __device__ __forceinline__ void gemm_core(
    const __half* __restrict__ Ah, const __half* __restrict__ Al,
    const __half* __restrict__ Bh,
    const float* __restrict__ bias, const float* __restrict__ gamma,
    float* __restrict__ C, __half* __restrict__ Oh, __half* __restrict__ Ol,
    int bm, int bn)
{
    extern __shared__ __half smbuf[];
    const uint32_t smu = s2u(smbuf);
    const int tid  = threadIdx.x;
    const int lane = tid & 31;
    const int wid  = tid >> 5;
    const int wm   = wid & 1;        // 2 warps along M (64 rows)
    const int wn   = wid >> 1;       // 4 warps along N (64 cols)

    float acc[4][8][4];
#pragma unroll
    for (int i = 0; i < 4; i++)
#pragma unroll
        for (int j = 0; j < 8; j++)
#pragma unroll
            for (int q = 0; q < 4; q++) acc[i][j][q] = 0.f;

#define ISSUE(c_) do {                                                         \
        const int c__ = (c_);                                                  \
        const uint32_t sb = smu + (uint32_t)((c__ % NSTG) * STAGE_B);          \
        const int k0 = c__ * BK;                                               \
        _Pragma("unroll")                                                      \
        for (int arr = 0; arr < 3; arr++){                                     \
            const __half* s = (arr==0)?Ah:(arr==1)?Al:Bh;                      \
            const int row0 = (arr < 2) ? bm : bn;                              \
            const int nit  = (arr < 2) ? 4 : 8;                                \
            const uint32_t ab = sb + (uint32_t)(arr * A_TB);                   \
            _Pragma("unroll")                                                  \
            for (int it = 0; it < nit; it++){                                  \
                int id = tid + it*NTHR;                                        \
                int r = id >> 3, cg = id & 7;                                  \
                cp16(ab + (uint32_t)(r*LDS_ + cg*8)*2,                         \
                     s + (size_t)(row0 + r)*DM + k0 + cg*8);                   \
            }                                                                  \
        }                                                                      \
        CP_COMMIT();                                                           \
    } while(0)

    ISSUE(0);
    ISSUE(1);
    for (int c = 0; c < NCH; c++){
        if (c + 1 < NCH){
            asm volatile("cp.async.wait_group 1;" ::: "memory");
        } else {
            asm volatile("cp.async.wait_group 0;" ::: "memory");
        }
        __syncthreads();                 // chunk c ready; all warps done with c-1
        if (c + 2 < NCH) ISSUE(c + 2);   // buffer (c+2)%3 free (read in c-1)

        const uint32_t sb = smu + (uint32_t)((c % NSTG) * STAGE_B);
#pragma unroll
        for (int ks = 0; ks < 4; ks++){
            uint32_t bf[4][4];
#pragma unroll
            for (int np = 0; np < 4; np++){
                uint32_t bd = sb + (uint32_t)(2*A_TB) + (uint32_t)(
                    (wn*64 + np*16 + (lane & 15))*LDS_ + ks*16 + (lane >> 4)*8)*2;
                LDM4(bf[np], bd);        // B stored [N][K]: non-trans = col frag
            }
#pragma unroll
            for (int mt = 0; mt < 4; mt++){
                uint32_t ah[4], al[4];
                uint32_t ad = sb + (uint32_t)(
                    (wm*64 + mt*16 + (lane & 15))*LDS_ + ks*16 + (lane >> 4)*8)*2;
                LDM4(ah, ad);
                LDM4(al, ad + A_TB);
#pragma unroll
                for (int nt = 0; nt < 8; nt++){
                    const int np = nt >> 1, sub = nt & 1;
                    MMA(acc[mt][nt], ah, bf[np][sub], bf[np][sub+2]);
                    MMA(acc[mt][nt], al, bf[np][sub], bf[np][sub+2]);
                }
            }
        }
    }
#undef ISSUE

    // ---- epilogue ----
#pragma unroll
    for (int mt = 0; mt < 4; mt++){
        const int row0 = bm + wm*64 + mt*16 + (lane >> 2);
        if (EPI == 0){
#pragma unroll
            for (int nt = 0; nt < 8; nt++){
                const int col = bn + wn*64 + nt*8 + (lane & 3)*2;
                const float bx = bias[col], by = bias[col+1];
                float2 o0, o1;
                o0.x = acc[mt][nt][0] + bx;  o0.y = acc[mt][nt][1] + by;
                o1.x = acc[mt][nt][2] + bx;  o1.y = acc[mt][nt][3] + by;
                *reinterpret_cast<float2*>(C + (size_t)row0*DM + col) = o0;
                *reinterpret_cast<float2*>(C + (size_t)(row0+8)*DM + col) = o1;
            }
        } else {
            // per-head xnorm: this warp's 64 cols == one head
            float s0 = 0.f, s1 = 0.f;
#pragma unroll
            for (int nt = 0; nt < 8; nt++){
                const int col = bn + wn*64 + nt*8 + (lane & 3)*2;
                const float bx = bias[col], by = bias[col+1];
                acc[mt][nt][0] += bx; acc[mt][nt][1] += by;
                acc[mt][nt][2] += bx; acc[mt][nt][3] += by;
                s0 += acc[mt][nt][0]*acc[mt][nt][0] + acc[mt][nt][1]*acc[mt][nt][1];
                s1 += acc[mt][nt][2]*acc[mt][nt][2] + acc[mt][nt][3]*acc[mt][nt][3];
            }
            s0 += __shfl_xor_sync(0xffffffffu, s0, 1);
            s0 += __shfl_xor_sync(0xffffffffu, s0, 2);
            s1 += __shfl_xor_sync(0xffffffffu, s1, 1);
            s1 += __shfl_xor_sync(0xffffffffu, s1, 2);
            const int head = (bn >> 6) + wn;
            const float g = __ldg(gamma + head);
            const float sc0 = g * rsqrtf(s0);
            const float sc1 = g * rsqrtf(s1);
#pragma unroll
            for (int nt = 0; nt < 8; nt++){
                const int col = bn + wn*64 + nt*8 + (lane & 3)*2;
                float x0 = acc[mt][nt][0]*sc0, x1 = acc[mt][nt][1]*sc0;
                float x2 = acc[mt][nt][2]*sc1, x3 = acc[mt][nt][3]*sc1;
                __half h0 = __float2half(x0), h1 = __float2half(x1);
                __half h2 = __float2half(x2), h3 = __float2half(x3);
                __half l0 = __float2half(x0 - __half2float(h0));
                __half l1 = __float2half(x1 - __half2float(h1));
                __half l2 = __float2half(x2 - __half2float(h2));
                __half l3 = __float2half(x3 - __half2float(h3));
                *reinterpret_cast<uint32_t*>(Oh + (size_t)row0*DM + col) =
                    (uint32_t)__half_as_ushort(h0) | ((uint32_t)__half_as_ushort(h1)<<16);
                *reinterpret_cast<uint32_t*>(Ol + (size_t)row0*DM + col) =
                    (uint32_t)__half_as_ushort(l0) | ((uint32_t)__half_as_ushort(l1)<<16);
                *reinterpret_cast<uint32_t*>(Oh + (size_t)(row0+8)*DM + col) =
                    (uint32_t)__half_as_ushort(h2) | ((uint32_t)__half_as_ushort(h3)<<16);
                *reinterpret_cast<uint32_t*>(Ol + (size_t)(row0+8)*DM + col) =
                    (uint32_t)__half_as_ushort(l2) | ((uint32_t)__half_as_ushort(l3)<<16);
            }
        }
    }
}

// ---------------- GEMM wrappers ----------------------------------------------
__global__ void __launch_bounds__(NTHR, 1) proj_mma(
    const float* __restrict__ bq, const float* __restrict__ bk, const float* __restrict__ bv,
    const float* __restrict__ gamma)
{
    const int z = blockIdx.z;
    if (z == 0){
        gemm_core<1>(g_inh[0], g_inl[0], g_w[0], bq, gamma,
                     nullptr, g_qnh, g_qnl, blockIdx.y * BM, blockIdx.x * BN);
    } else {
        const float* bias = (z == 1) ? bk : bv;
        gemm_core<0>(g_inh[z], g_inl[z], g_w[z], bias, nullptr,
                     g_kvin[z-1], nullptr, nullptr, blockIdx.y * BM, blockIdx.x * BN);
    }
}
__global__ void __launch_bounds__(NTHR, 1) out_mma(
    const float* __restrict__ bo, float* __restrict__ out)
{
    const int b = blockIdx.z;
    gemm_core<0>(g_qnh + (size_t)b*SEQ*DM, g_qnl + (size_t)b*SEQ*DM,
                 g_w2 + (size_t)b*DM*DM, bo, nullptr,
                 out + (size_t)b*SEQ*DM, nullptr, nullptr,
                 blockIdx.y * BM, blockIdx.x * BN);
}

// ---------------- split / convert kernels --------------------------------------
__global__ void __launch_bounds__(256) split_in(
    const float* __restrict__ q, const float* __restrict__ k, const float* __restrict__ v)
{
    int z = blockIdx.z;
    const float* s = (z == 0) ? q : (z == 1) ? k : v;
    size_t i4 = (size_t)blockIdx.x * 256 + threadIdx.x;
    float4 x = *reinterpret_cast<const float4*>(s + i4*4);
    store_hl(&g_inh[z][i4*4], &g_inl[z][i4*4], x);
}
__global__ void __launch_bounds__(256) conv_w(
    const float* __restrict__ wq, const float* __restrict__ wk, const float* __restrict__ wv)
{
    int z = blockIdx.z;
    const float* s = (z == 0) ? wq : (z == 1) ? wk : wv;
    size_t i4 = (size_t)blockIdx.x * 256 + threadIdx.x;
    float4 x = *reinterpret_cast<const float4*>(s + i4*4);
    __half h[4] = {__float2half(x.x), __float2half(x.y), __float2half(x.z), __float2half(x.w)};
    *reinterpret_cast<uint2*>(&g_w[z][i4*4]) = make_uint2(
        (uint32_t)__half_as_ushort(h[0]) | ((uint32_t)__half_as_ushort(h[1])<<16),
        (uint32_t)__half_as_ushort(h[2]) | ((uint32_t)__half_as_ushort(h[3])<<16));
}

// ---------------- kv accumulation ----------------------------------------------
__global__ void zero_kv(){
    int i = blockIdx.x * 256 + threadIdx.x;
    if (i < BATCH*H*64*64) g_kv[i] = 0.f;
}
__global__ void __launch_bounds__(256) kv_kernel()
{
    const int bh = blockIdx.x, chunk = blockIdx.y;
    const int b = bh >> 4, h = bh & 15;
    const float* kbase = g_kvin[0] + (size_t)b*SEQ*DM + h*64;
    const float* vbase = g_kvin[1] + (size_t)b*SEQ*DM + h*64;
    __shared__ float ks[8][64], vs[8][64];
    const int tid = threadIdx.x;
    const int tj = tid & 15, ti = tid >> 4;
    float acc[4][4];
#pragma unroll
    for (int i = 0; i < 4; i++)
#pragma unroll
        for (int j = 0; j < 4; j++) acc[i][j] = 0.f;
    const int n0 = chunk * (SEQ/16);
    for (int nn = n0; nn < n0 + SEQ/16; nn += 8){
        int l = tid & 127, row = l >> 4, c = (l & 15) << 2;
        const float* src = (tid < 128) ? kbase : vbase;
        float* dst = (tid < 128) ? &ks[row][c] : &vs[row][c];
        *reinterpret_cast<float4*>(dst) =
            *reinterpret_cast<const float4*>(src + (size_t)(nn+row)*DM + c);
        __syncthreads();
#pragma unroll
        for (int r = 0; r < 8; r++){
            float kr[4], vr[4];
            *reinterpret_cast<float4*>(kr) = *reinterpret_cast<const float4*>(&ks[r][ti*4]);
            *reinterpret_cast<float4*>(vr) = *reinterpret_cast<const float4*>(&vs[r][tj*4]);
#pragma unroll
            for (int i = 0; i < 4; i++)
#pragma unroll
                for (int j = 0; j < 4; j++) acc[i][j] += kr[i] * vr[j];
        }
        __syncthreads();
    }
    float* kvp = g_kv + (size_t)bh * 4096;
#pragma unroll
    for (int i = 0; i < 4; i++)
#pragma unroll
        for (int j = 0; j < 4; j++)
            atomicAdd(&kvp[(ti*4+i)*64 + tj*4 + j], acc[i][j]);
}

// ---------------- fold: xnorm(kv) @ Wo^T -> W2 (fp16) --------------------------
__global__ void __launch_bounds__(256) fold_kernel(
    const float* __restrict__ Wo, const float* __restrict__ gamma)
{
    const int bh = blockIdx.x, jc = blockIdx.y;
    const int b = bh >> 4, h = bh & 15;
    const int j0 = jc * 128;
    __shared__ float kvn[64][65];
    __shared__ float rn[64];
    const int tid = threadIdx.x;
    const float* kvsrc = g_kv + (size_t)bh * 4096;
    for (int l = tid; l < 4096; l += 256) kvn[l>>6][l&63] = kvsrc[l];
    __syncthreads();
    if (tid < 64){
        float s = 0.f;
#pragma unroll 16
        for (int d = 0; d < 64; d++){ float x = kvn[tid][d]; s += x*x; }
        rn[tid] = gamma[h] * rsqrtf(s);
    }
    __syncthreads();
    const int i = tid & 63, jg = tid >> 6;
    const float sc = rn[i];
    __half* w2 = g_w2 + (size_t)b*DM*DM;
    for (int j = jg; j < 128; j += 4){
        const float* wr = Wo + (size_t)(j0+j)*DM + h*64;
        float acc = 0.f;
#pragma unroll 16
        for (int d = 0; d < 64; d++) acc += kvn[i][d] * __ldg(wr + d);
        w2[(size_t)(j0+j)*DM + h*64 + i] = __float2half(acc * sc);
    }
}

// ---------------- launch ----------------------------------------------------------
extern "C" void kernel_launch(void* const* d_in, const int* in_sizes, int n_in,
                              void* d_out, int out_size)
{
    const float* queries = (const float*)d_in[0];
    const float* keys    = (const float*)d_in[1];
    const float* values  = (const float*)d_in[2];
    const float* Wq = (const float*)d_in[3];
    const float* bq = (const float*)d_in[4];
    const float* Wk = (const float*)d_in[5];
    const float* bk = (const float*)d_in[6];
    const float* Wv = (const float*)d_in[7];
    const float* bv = (const float*)d_in[8];
    const float* Wo = (const float*)d_in[9];
    const float* bo = (const float*)d_in[10];
    const float* gamma = (const float*)d_in[11];
    float* out = (float*)d_out;

    cudaFuncSetAttribute(proj_mma, cudaFuncAttributeMaxDynamicSharedMemorySize, DYN);
    cudaFuncSetAttribute(out_mma,  cudaFuncAttributeMaxDynamicSharedMemorySize, DYN);

    split_in<<<dim3((MTOT*DM/4)/256, 1, 3), 256>>>(queries, keys, values);
    conv_w<<<dim3((DM*DM/4)/256, 1, 3), 256>>>(Wq, Wk, Wv);
    zero_kv<<<(BATCH*H*64*64)/256, 256>>>();

    proj_mma<<<dim3(DM/BN, MTOT/BM, 3), NTHR, DYN>>>(bq, bk, bv, gamma);

    kv_kernel<<<dim3(BATCH*H, 16), 256>>>();
    fold_kernel<<<dim3(BATCH*H, 8), 256>>>(Wo, gamma);

    out_mma<<<dim3(DM/BN, SEQ/BM, BATCH), NTHR, DYN>>>(bo, out);
}

// round 9
// speedup vs baseline: 3.3676x; 1.0031x over previous
#include <cuda_runtime.h>
#include <cuda_fp16.h>
#include <cstdint>

#define DM 1024
#define H 16
#define BATCH 4
#define SEQ 8192
#define MTOT (BATCH*SEQ)

// GEMM tiling: CTA 128x256, warp 64x64 (2M x 4N warps, 256 threads)
#define BM 128
#define BN 256
#define BK 64
#define NCH (DM/BK)             // 16 K-chunks
#define LDS_ 72                 // 64 + 8 pad elems -> 144B row stride
#define A_TB (128*LDS_*2)       // 18432 B per A tile
#define B_TB (256*LDS_*2)       // 36864 B per B tile
#define STAGE_B (2*A_TB+B_TB)   // 73728 B (Ah, Al, Bh)
#define NSTG 3
#define DYN (NSTG*STAGE_B)      // 221184 B
#define NTHR 256

// ---------------- scratch ----------------------------------------------------
__device__ float g_kvin[2][(size_t)MTOT*DM];                  // k, v fp32
__device__ __half g_inh[3][(size_t)MTOT*DM];
__device__ __half g_inl[3][(size_t)MTOT*DM];
__device__ __half g_w[3][DM*DM];
__device__ __half g_qnh[(size_t)MTOT*DM];
__device__ __half g_qnl[(size_t)MTOT*DM];
__device__ __half g_w2[(size_t)BATCH*DM*DM];
__device__ float g_kv[BATCH*H*64*64];

// ---------------- helpers ------------------------------------------------------
static __device__ __forceinline__ uint32_t s2u(const void* p){
    uint32_t r;
    asm("{ .reg .u64 t; cvta.to.shared.u64 t, %1; cvt.u32.u64 %0, t; }" : "=r"(r) : "l"(p));
    return r;
}
static __device__ __forceinline__ void cp16(uint32_t dst, const void* src){
    asm volatile("cp.async.cg.shared.global [%0], [%1], 16;" :: "r"(dst), "l"(src));
}
#define CP_COMMIT() asm volatile("cp.async.commit_group;" ::: "memory")
#define LDM4(r, a) asm volatile( \
    "ldmatrix.sync.aligned.m8n8.x4.shared.b16 {%0,%1,%2,%3}, [%4];" \
    : "=r"((r)[0]),"=r"((r)[1]),"=r"((r)[2]),"=r"((r)[3]) : "r"(a))
#define MMA(d, a, b0_, b1_) asm volatile( \
    "mma.sync.aligned.m16n8k16.row.col.f32.f16.f16.f32 " \
    "{%0,%1,%2,%3},{%4,%5,%6,%7},{%8,%9},{%0,%1,%2,%3};" \
    : "+f"((d)[0]),"+f"((d)[1]),"+f"((d)[2]),"+f"((d)[3]) \
    : "r"((a)[0]),"r"((a)[1]),"r"((a)[2]),"r"((a)[3]), "r"(b0_),"r"(b1_))

static __device__ __forceinline__ void store_hl(__half* ph, __half* pl, float4 x){
    float v[4] = {x.x, x.y, x.z, x.w};
    uint32_t hw[4], lw[4];
#pragma unroll
    for (int i = 0; i < 4; i++){
        __half hb = __float2half(v[i]);
        __half lb = __float2half(v[i] - __half2float(hb));
        hw[i] = __half_as_ushort(hb);
        lw[i] = __half_as_ushort(lb);
    }
    *reinterpret_cast<uint2*>(ph) = make_uint2(hw[0]|(hw[1]<<16), hw[2]|(hw[3]<<16));
    *reinterpret_cast<uint2*>(pl) = make_uint2(lw[0]|(lw[1]<<16), lw[2]|(lw[3]<<16));
}

// ---------------- fp16 2-pass GEMM core: C = (Ah+Al) @ Bh^T + bias ------------
// EPI 0: bias + fp32 store.  EPI 1: bias + per-head xnorm + fp16 hi/lo store.
template<int EPI>
static __device__ __forceinline__ void gemm_core(
    const __half* __restrict__ Ah, const __half* __restrict__ Al,
    const __half* __restrict__ Bh,
    const float* __restrict__ bias, const float* __restrict__ gamma,
    float* __restrict__ C, __half* __restrict__ Oh, __half* __restrict__ Ol,
    int bm, int bn)
{
    extern __shared__ __half smbuf[];
    const uint32_t smu = s2u(smbuf);
    const int tid  = threadIdx.x;
    const int lane = tid & 31;
    const int wid  = tid >> 5;
    const int wm   = wid & 1;        // 2 warps along M (64 rows)
    const int wn   = wid >> 1;       // 4 warps along N (64 cols)

    // hoisted lane-dependent LDSM byte offsets (loop terms are constants)
    const uint32_t a_off = (uint32_t)((wm*64 + (lane & 15))*LDS_ + (lane >> 4)*8)*2;
    const uint32_t b_off = (uint32_t)(2*A_TB) +
                           (uint32_t)((wn*64 + (lane & 15))*LDS_ + (lane >> 4)*8)*2;

    float acc[4][8][4];
#pragma unroll
    for (int i = 0; i < 4; i++)
#pragma unroll
        for (int j = 0; j < 8; j++)
#pragma unroll
            for (int q = 0; q < 4; q++) acc[i][j][q] = 0.f;

#define ISSUE(c_) do {                                                         \
        const int c__ = (c_);                                                  \
        const uint32_t sb = smu + (uint32_t)((c__ % NSTG) * STAGE_B);          \
        const int k0 = c__ * BK;                                               \
        _Pragma("unroll")                                                      \
        for (int arr = 0; arr < 3; arr++){                                     \
            const __half* s = (arr==0)?Ah:(arr==1)?Al:Bh;                      \
            const int row0 = (arr < 2) ? bm : bn;                              \
            const int nit  = (arr < 2) ? 4 : 8;                                \
            const uint32_t ab = sb + (uint32_t)(arr * A_TB);                   \
            _Pragma("unroll")                                                  \
            for (int it = 0; it < nit; it++){                                  \
                int id = tid + it*NTHR;                                        \
                int r = id >> 3, cg = id & 7;                                  \
                cp16(ab + (uint32_t)(r*LDS_ + cg*8)*2,                         \
                     s + (size_t)(row0 + r)*DM + k0 + cg*8);                   \
            }                                                                  \
        }                                                                      \
        CP_COMMIT();                                                           \
    } while(0)

    ISSUE(0);
    ISSUE(1);
    for (int c = 0; c < NCH; c++){
        if (c + 1 < NCH){
            asm volatile("cp.async.wait_group 1;" ::: "memory");
        } else {
            asm volatile("cp.async.wait_group 0;" ::: "memory");
        }
        __syncthreads();                 // chunk c ready; all warps done with c-1
        if (c + 2 < NCH) ISSUE(c + 2);   // buffer (c+2)%3 free (read in c-1)

        const uint32_t sb = smu + (uint32_t)((c % NSTG) * STAGE_B);
#pragma unroll
        for (int ks = 0; ks < 4; ks++){
            uint32_t bf[4][4];
#pragma unroll
            for (int np = 0; np < 4; np++)
                LDM4(bf[np], sb + b_off + (uint32_t)(np*16*LDS_ + ks*16)*2);
#pragma unroll
            for (int mt = 0; mt < 4; mt++){
                uint32_t ah[4], al[4];
                const uint32_t ad = sb + a_off + (uint32_t)(mt*16*LDS_ + ks*16)*2;
                LDM4(ah, ad);
                LDM4(al, ad + A_TB);
                // all 8 nt with ah first, then all 8 with al:
                // accumulator-reuse distance = 8 independent MMAs
#pragma unroll
                for (int nt = 0; nt < 8; nt++){
                    const int np = nt >> 1, sub = nt & 1;
                    MMA(acc[mt][nt], ah, bf[np][sub], bf[np][sub+2]);
                }
#pragma unroll
                for (int nt = 0; nt < 8; nt++){
                    const int np = nt >> 1, sub = nt & 1;
                    MMA(acc[mt][nt], al, bf[np][sub], bf[np][sub+2]);
                }
            }
        }
    }
#undef ISSUE

    // ---- epilogue ----
#pragma unroll
    for (int mt = 0; mt < 4; mt++){
        const int row0 = bm + wm*64 + mt*16 + (lane >> 2);
        if (EPI == 0){
#pragma unroll
            for (int nt = 0; nt < 8; nt++){
                const int col = bn + wn*64 + nt*8 + (lane & 3)*2;
                const float bx = bias[col], by = bias[col+1];
                float2 o0, o1;
                o0.x = acc[mt][nt][0] + bx;  o0.y = acc[mt][nt][1] + by;
                o1.x = acc[mt][nt][2] + bx;  o1.y = acc[mt][nt][3] + by;
                *reinterpret_cast<float2*>(C + (size_t)row0*DM + col) = o0;
                *reinterpret_cast<float2*>(C + (size_t)(row0+8)*DM + col) = o1;
            }
        } else {
            // per-head xnorm: this warp's 64 cols == one head
            float s0 = 0.f, s1 = 0.f;
#pragma unroll
            for (int nt = 0; nt < 8; nt++){
                const int col = bn + wn*64 + nt*8 + (lane & 3)*2;
                const float bx = bias[col], by = bias[col+1];
                acc[mt][nt][0] += bx; acc[mt][nt][1] += by;
                acc[mt][nt][2] += bx; acc[mt][nt][3] += by;
                s0 += acc[mt][nt][0]*acc[mt][nt][0] + acc[mt][nt][1]*acc[mt][nt][1];
                s1 += acc[mt][nt][2]*acc[mt][nt][2] + acc[mt][nt][3]*acc[mt][nt][3];
            }
            s0 += __shfl_xor_sync(0xffffffffu, s0, 1);
            s0 += __shfl_xor_sync(0xffffffffu, s0, 2);
            s1 += __shfl_xor_sync(0xffffffffu, s1, 1);
            s1 += __shfl_xor_sync(0xffffffffu, s1, 2);
            const int head = (bn >> 6) + wn;
            const float g = __ldg(gamma + head);
            const float sc0 = g * rsqrtf(s0);
            const float sc1 = g * rsqrtf(s1);
#pragma unroll
            for (int nt = 0; nt < 8; nt++){
                const int col = bn + wn*64 + nt*8 + (lane & 3)*2;
                float x0 = acc[mt][nt][0]*sc0, x1 = acc[mt][nt][1]*sc0;
                float x2 = acc[mt][nt][2]*sc1, x3 = acc[mt][nt][3]*sc1;
                __half h0 = __float2half(x0), h1 = __float2half(x1);
                __half h2 = __float2half(x2), h3 = __float2half(x3);
                __half l0 = __float2half(x0 - __half2float(h0));
                __half l1 = __float2half(x1 - __half2float(h1));
                __half l2 = __float2half(x2 - __half2float(h2));
                __half l3 = __float2half(x3 - __half2float(h3));
                *reinterpret_cast<uint32_t*>(Oh + (size_t)row0*DM + col) =
                    (uint32_t)__half_as_ushort(h0) | ((uint32_t)__half_as_ushort(h1)<<16);
                *reinterpret_cast<uint32_t*>(Ol + (size_t)row0*DM + col) =
                    (uint32_t)__half_as_ushort(l0) | ((uint32_t)__half_as_ushort(l1)<<16);
                *reinterpret_cast<uint32_t*>(Oh + (size_t)(row0+8)*DM + col) =
                    (uint32_t)__half_as_ushort(h2) | ((uint32_t)__half_as_ushort(h3)<<16);
                *reinterpret_cast<uint32_t*>(Ol + (size_t)(row0+8)*DM + col) =
                    (uint32_t)__half_as_ushort(l2) | ((uint32_t)__half_as_ushort(l3)<<16);
            }
        }
    }
}

// ---------------- GEMM wrappers ----------------------------------------------
__global__ void __launch_bounds__(NTHR, 1) proj_mma(
    const float* __restrict__ bq, const float* __restrict__ bk, const float* __restrict__ bv,
    const float* __restrict__ gamma)
{
    const int z = blockIdx.z;
    if (z == 0){
        gemm_core<1>(g_inh[0], g_inl[0], g_w[0], bq, gamma,
                     nullptr, g_qnh, g_qnl, blockIdx.y * BM, blockIdx.x * BN);
    } else {
        const float* bias = (z == 1) ? bk : bv;
        gemm_core<0>(g_inh[z], g_inl[z], g_w[z], bias, nullptr,
                     g_kvin[z-1], nullptr, nullptr, blockIdx.y * BM, blockIdx.x * BN);
    }
}
__global__ void __launch_bounds__(NTHR, 1) out_mma(
    const float* __restrict__ bo, float* __restrict__ out)
{
    const int b = blockIdx.z;
    gemm_core<0>(g_qnh + (size_t)b*SEQ*DM, g_qnl + (size_t)b*SEQ*DM,
                 g_w2 + (size_t)b*DM*DM, bo, nullptr,
                 out + (size_t)b*SEQ*DM, nullptr, nullptr,
                 blockIdx.y * BM, blockIdx.x * BN);
}

// ---------------- split / convert kernels --------------------------------------
__global__ void __launch_bounds__(256) split_in(
    const float* __restrict__ q, const float* __restrict__ k, const float* __restrict__ v)
{
    int z = blockIdx.z;
    const float* s = (z == 0) ? q : (z == 1) ? k : v;
    size_t i4 = (size_t)blockIdx.x * 256 + threadIdx.x;
    float4 x = *reinterpret_cast<const float4*>(s + i4*4);
    store_hl(&g_inh[z][i4*4], &g_inl[z][i4*4], x);
}
__global__ void __launch_bounds__(256) conv_w(
    const float* __restrict__ wq, const float* __restrict__ wk, const float* __restrict__ wv)
{
    int z = blockIdx.z;
    const float* s = (z == 0) ? wq : (z == 1) ? wk : wv;
    size_t i4 = (size_t)blockIdx.x * 256 + threadIdx.x;
    float4 x = *reinterpret_cast<const float4*>(s + i4*4);
    __half h[4] = {__float2half(x.x), __float2half(x.y), __float2half(x.z), __float2half(x.w)};
    *reinterpret_cast<uint2*>(&g_w[z][i4*4]) = make_uint2(
        (uint32_t)__half_as_ushort(h[0]) | ((uint32_t)__half_as_ushort(h[1])<<16),
        (uint32_t)__half_as_ushort(h[2]) | ((uint32_t)__half_as_ushort(h[3])<<16));
}

// ---------------- kv accumulation ----------------------------------------------
__global__ void zero_kv(){
    int i = blockIdx.x * 256 + threadIdx.x;
    if (i < BATCH*H*64*64) g_kv[i] = 0.f;
}
__global__ void __launch_bounds__(256) kv_kernel()
{
    const int bh = blockIdx.x, chunk = blockIdx.y;
    const int b = bh >> 4, h = bh & 15;
    const float* kbase = g_kvin[0] + (size_t)b*SEQ*DM + h*64;
    const float* vbase = g_kvin[1] + (size_t)b*SEQ*DM + h*64;
    __shared__ float ks[8][64], vs[8][64];
    const int tid = threadIdx.x;
    const int tj = tid & 15, ti = tid >> 4;
    float acc[4][4];
#pragma unroll
    for (int i = 0; i < 4; i++)
#pragma unroll
        for (int j = 0; j < 4; j++) acc[i][j] = 0.f;
    const int n0 = chunk * (SEQ/16);
    for (int nn = n0; nn < n0 + SEQ/16; nn += 8){
        int l = tid & 127, row = l >> 4, c = (l & 15) << 2;
        const float* src = (tid < 128) ? kbase : vbase;
        float* dst = (tid < 128) ? &ks[row][c] : &vs[row][c];
        *reinterpret_cast<float4*>(dst) =
            *reinterpret_cast<const float4*>(src + (size_t)(nn+row)*DM + c);
        __syncthreads();
#pragma unroll
        for (int r = 0; r < 8; r++){
            float kr[4], vr[4];
            *reinterpret_cast<float4*>(kr) = *reinterpret_cast<const float4*>(&ks[r][ti*4]);
            *reinterpret_cast<float4*>(vr) = *reinterpret_cast<const float4*>(&vs[r][tj*4]);
#pragma unroll
            for (int i = 0; i < 4; i++)
#pragma unroll
                for (int j = 0; j < 4; j++) acc[i][j] += kr[i] * vr[j];
        }
        __syncthreads();
    }
    float* kvp = g_kv + (size_t)bh * 4096;
#pragma unroll
    for (int i = 0; i < 4; i++)
#pragma unroll
        for (int j = 0; j < 4; j++)
            atomicAdd(&kvp[(ti*4+i)*64 + tj*4 + j], acc[i][j]);
}

// ---------------- fold: xnorm(kv) @ Wo^T -> W2 (fp16) --------------------------
__global__ void __launch_bounds__(256) fold_kernel(
    const float* __restrict__ Wo, const float* __restrict__ gamma)
{
    const int bh = blockIdx.x, jc = blockIdx.y;
    const int b = bh >> 4, h = bh & 15;
    const int j0 = jc * 128;
    __shared__ float kvn[64][65];
    __shared__ float rn[64];
    const int tid = threadIdx.x;
    const float* kvsrc = g_kv + (size_t)bh * 4096;
    for (int l = tid; l < 4096; l += 256) kvn[l>>6][l&63] = kvsrc[l];
    __syncthreads();
    if (tid < 64){
        float s = 0.f;
#pragma unroll 16
        for (int d = 0; d < 64; d++){ float x = kvn[tid][d]; s += x*x; }
        rn[tid] = gamma[h] * rsqrtf(s);
    }
    __syncthreads();
    const int i = tid & 63, jg = tid >> 6;
    const float sc = rn[i];
    __half* w2 = g_w2 + (size_t)b*DM*DM;
    for (int j = jg; j < 128; j += 4){
        const float* wr = Wo + (size_t)(j0+j)*DM + h*64;
        float acc = 0.f;
#pragma unroll 16
        for (int d = 0; d < 64; d++) acc += kvn[i][d] * __ldg(wr + d);
        w2[(size_t)(j0+j)*DM + h*64 + i] = __float2half(acc * sc);
    }
}

// ---------------- launch ----------------------------------------------------------
extern "C" void kernel_launch(void* const* d_in, const int* in_sizes, int n_in,
                              void* d_out, int out_size)
{
    const float* queries = (const float*)d_in[0];
    const float* keys    = (const float*)d_in[1];
    const float* values  = (const float*)d_in[2];
    const float* Wq = (const float*)d_in[3];
    const float* bq = (const float*)d_in[4];
    const float* Wk = (const float*)d_in[5];
    const float* bk = (const float*)d_in[6];
    const float* Wv = (const float*)d_in[7];
    const float* bv = (const float*)d_in[8];
    const float* Wo = (const float*)d_in[9];
    const float* bo = (const float*)d_in[10];
    const float* gamma = (const float*)d_in[11];
    float* out = (float*)d_out;

    cudaFuncSetAttribute(proj_mma, cudaFuncAttributeMaxDynamicSharedMemorySize, DYN);
    cudaFuncSetAttribute(out_mma,  cudaFuncAttributeMaxDynamicSharedMemorySize, DYN);

    split_in<<<dim3((MTOT*DM/4)/256, 1, 3), 256>>>(queries, keys, values);
    conv_w<<<dim3((DM*DM/4)/256, 1, 3), 256>>>(Wq, Wk, Wv);
    zero_kv<<<(BATCH*H*64*64)/256, 256>>>();

    proj_mma<<<dim3(DM/BN, MTOT/BM, 3), NTHR, DYN>>>(bq, bk, bv, gamma);

    kv_kernel<<<dim3(BATCH*H, 16), 256>>>();
    fold_kernel<<<dim3(BATCH*H, 8), 256>>>(Wo, gamma);

    out_mma<<<dim3(DM/BN, SEQ/BM, BATCH), NTHR, DYN>>>(bo, out);
}

// round 10
// speedup vs baseline: 3.4450x; 1.0230x over previous
#include <cuda_runtime.h>
#include <cuda_fp16.h>
#include <cstdint>

#define DM 1024
#define H 16
#define BATCH 4
#define SEQ 8192
#define MTOT (BATCH*SEQ)

// GEMM tiling: CTA 128x128, warp 32x64 (4M x 2N warps, 256 threads), 2 CTAs/SM
#define BM 128
#define BN 128
#define BK 64
#define NCH (DM/BK)             // 16 K-chunks
#define LDS_ 72                 // 64 + 8 pad elems -> 144B row stride
#define TB (128*LDS_*2)         // 18432 B per operand tile (128 rows)
#define STAGE_B (3*TB)          // 55296 B (Ah, Al, Bh)
#define NSTG 2
#define DYN (NSTG*STAGE_B)      // 110592 B -> 2 CTAs per SM
#define NTHR 256

// ---------------- scratch ----------------------------------------------------
__device__ float g_kvin[2][(size_t)MTOT*DM];                  // k, v fp32
__device__ __half g_inh[3][(size_t)MTOT*DM];
__device__ __half g_inl[3][(size_t)MTOT*DM];
__device__ __half g_w[3][DM*DM];
__device__ __half g_qnh[(size_t)MTOT*DM];
__device__ __half g_qnl[(size_t)MTOT*DM];
__device__ __half g_w2[(size_t)BATCH*DM*DM];
__device__ float g_kv[BATCH*H*64*64];

// ---------------- helpers ------------------------------------------------------
static __device__ __forceinline__ uint32_t s2u(const void* p){
    uint32_t r;
    asm("{ .reg .u64 t; cvta.to.shared.u64 t, %1; cvt.u32.u64 %0, t; }" : "=r"(r) : "l"(p));
    return r;
}
static __device__ __forceinline__ void cp16(uint32_t dst, const void* src){
    asm volatile("cp.async.cg.shared.global [%0], [%1], 16;" :: "r"(dst), "l"(src));
}
#define CP_COMMIT() asm volatile("cp.async.commit_group;" ::: "memory")
#define LDM4(r, a) asm volatile( \
    "ldmatrix.sync.aligned.m8n8.x4.shared.b16 {%0,%1,%2,%3}, [%4];" \
    : "=r"((r)[0]),"=r"((r)[1]),"=r"((r)[2]),"=r"((r)[3]) : "r"(a))
#define MMA(d, a, b0_, b1_) asm volatile( \
    "mma.sync.aligned.m16n8k16.row.col.f32.f16.f16.f32 " \
    "{%0,%1,%2,%3},{%4,%5,%6,%7},{%8,%9},{%0,%1,%2,%3};" \
    : "+f"((d)[0]),"+f"((d)[1]),"+f"((d)[2]),"+f"((d)[3]) \
    : "r"((a)[0]),"r"((a)[1]),"r"((a)[2]),"r"((a)[3]), "r"(b0_),"r"(b1_))

static __device__ __forceinline__ void store_hl(__half* ph, __half* pl, float4 x){
    float v[4] = {x.x, x.y, x.z, x.w};
    uint32_t hw[4], lw[4];
#pragma unroll
    for (int i = 0; i < 4; i++){
        __half hb = __float2half(v[i]);
        __half lb = __float2half(v[i] - __half2float(hb));
        hw[i] = __half_as_ushort(hb);
        lw[i] = __half_as_ushort(lb);
    }
    *reinterpret_cast<uint2*>(ph) = make_uint2(hw[0]|(hw[1]<<16), hw[2]|(hw[3]<<16));
    *reinterpret_cast<uint2*>(pl) = make_uint2(lw[0]|(lw[1]<<16), lw[2]|(lw[3]<<16));
}

// ---------------- fp16 2-pass GEMM core: C = (Ah+Al) @ Bh^T + bias ------------
// EPI 0: bias + fp32 store.  EPI 1: bias + per-head xnorm + fp16 hi/lo store.
template<int EPI>
static __device__ __forceinline__ void gemm_core(
    const __half* __restrict__ Ah, const __half* __restrict__ Al,
    const __half* __restrict__ Bh,
    const float* __restrict__ bias, const float* __restrict__ gamma,
    float* __restrict__ C, __half* __restrict__ Oh, __half* __restrict__ Ol,
    int bm, int bn)
{
    extern __shared__ __half smbuf[];
    const uint32_t smu = s2u(smbuf);
    const int tid  = threadIdx.x;
    const int lane = tid & 31;
    const int wid  = tid >> 5;
    const int wm   = wid & 3;        // 4 warps along M (32 rows)
    const int wn   = wid >> 2;       // 2 warps along N (64 cols)

    const uint32_t a_off = (uint32_t)((wm*32 + (lane & 15))*LDS_ + (lane >> 4)*8)*2;
    const uint32_t b_off = (uint32_t)(2*TB) +
                           (uint32_t)((wn*64 + (lane & 15))*LDS_ + (lane >> 4)*8)*2;

    float acc[2][8][4];
#pragma unroll
    for (int i = 0; i < 2; i++)
#pragma unroll
        for (int j = 0; j < 8; j++)
#pragma unroll
            for (int q = 0; q < 4; q++) acc[i][j][q] = 0.f;

#define ISSUE(c_) do {                                                         \
        const int c__ = (c_);                                                  \
        const uint32_t sb = smu + (uint32_t)((c__ & 1) * STAGE_B);             \
        const int k0 = c__ * BK;                                               \
        _Pragma("unroll")                                                      \
        for (int arr = 0; arr < 3; arr++){                                     \
            const __half* s = (arr==0)?Ah:(arr==1)?Al:Bh;                      \
            const int row0 = (arr < 2) ? bm : bn;                              \
            const uint32_t ab = sb + (uint32_t)(arr * TB);                     \
            _Pragma("unroll")                                                  \
            for (int it = 0; it < 4; it++){                                    \
                int id = tid + it*NTHR;                                        \
                int r = id >> 3, cg = id & 7;                                  \
                cp16(ab + (uint32_t)(r*LDS_ + cg*8)*2,                         \
                     s + (size_t)(row0 + r)*DM + k0 + cg*8);                   \
            }                                                                  \
        }                                                                      \
        CP_COMMIT();                                                           \
    } while(0)

    ISSUE(0);
    for (int c = 0; c < NCH; c++){
        if (c + 1 < NCH){
            ISSUE(c + 1);
            asm volatile("cp.async.wait_group 1;" ::: "memory");
        } else {
            asm volatile("cp.async.wait_group 0;" ::: "memory");
        }
        __syncthreads();

        const uint32_t sb = smu + (uint32_t)((c & 1) * STAGE_B);
#pragma unroll
        for (int ks = 0; ks < 4; ks++){
            uint32_t bf[4][4];
#pragma unroll
            for (int np = 0; np < 4; np++)
                LDM4(bf[np], sb + b_off + (uint32_t)(np*16*LDS_ + ks*16)*2);
#pragma unroll
            for (int mt = 0; mt < 2; mt++){
                uint32_t ah[4], al[4];
                const uint32_t ad = sb + a_off + (uint32_t)(mt*16*LDS_ + ks*16)*2;
                LDM4(ah, ad);
                LDM4(al, ad + TB);
#pragma unroll
                for (int nt = 0; nt < 8; nt++){
                    const int np = nt >> 1, sub = nt & 1;
                    MMA(acc[mt][nt], ah, bf[np][sub], bf[np][sub+2]);
                }
#pragma unroll
                for (int nt = 0; nt < 8; nt++){
                    const int np = nt >> 1, sub = nt & 1;
                    MMA(acc[mt][nt], al, bf[np][sub], bf[np][sub+2]);
                }
            }
        }
        __syncthreads();
    }
#undef ISSUE

    // ---- epilogue ----
#pragma unroll
    for (int mt = 0; mt < 2; mt++){
        const int row0 = bm + wm*32 + mt*16 + (lane >> 2);
        if (EPI == 0){
#pragma unroll
            for (int nt = 0; nt < 8; nt++){
                const int col = bn + wn*64 + nt*8 + (lane & 3)*2;
                const float bx = bias[col], by = bias[col+1];
                float2 o0, o1;
                o0.x = acc[mt][nt][0] + bx;  o0.y = acc[mt][nt][1] + by;
                o1.x = acc[mt][nt][2] + bx;  o1.y = acc[mt][nt][3] + by;
                *reinterpret_cast<float2*>(C + (size_t)row0*DM + col) = o0;
                *reinterpret_cast<float2*>(C + (size_t)(row0+8)*DM + col) = o1;
            }
        } else {
            // per-head xnorm: this warp's 64 cols == one head
            float s0 = 0.f, s1 = 0.f;
#pragma unroll
            for (int nt = 0; nt < 8; nt++){
                const int col = bn + wn*64 + nt*8 + (lane & 3)*2;
                const float bx = bias[col], by = bias[col+1];
                acc[mt][nt][0] += bx; acc[mt][nt][1] += by;
                acc[mt][nt][2] += bx; acc[mt][nt][3] += by;
                s0 += acc[mt][nt][0]*acc[mt][nt][0] + acc[mt][nt][1]*acc[mt][nt][1];
                s1 += acc[mt][nt][2]*acc[mt][nt][2] + acc[mt][nt][3]*acc[mt][nt][3];
            }
            s0 += __shfl_xor_sync(0xffffffffu, s0, 1);
            s0 += __shfl_xor_sync(0xffffffffu, s0, 2);
            s1 += __shfl_xor_sync(0xffffffffu, s1, 1);
            s1 += __shfl_xor_sync(0xffffffffu, s1, 2);
            const int head = (bn >> 6) + wn;
            const float g = __ldg(gamma + head);
            const float sc0 = g * rsqrtf(s0);
            const float sc1 = g * rsqrtf(s1);
#pragma unroll
            for (int nt = 0; nt < 8; nt++){
                const int col = bn + wn*64 + nt*8 + (lane & 3)*2;
                float x0 = acc[mt][nt][0]*sc0, x1 = acc[mt][nt][1]*sc0;
                float x2 = acc[mt][nt][2]*sc1, x3 = acc[mt][nt][3]*sc1;
                __half h0 = __float2half(x0), h1 = __float2half(x1);
                __half h2 = __float2half(x2), h3 = __float2half(x3);
                __half l0 = __float2half(x0 - __half2float(h0));
                __half l1 = __float2half(x1 - __half2float(h1));
                __half l2 = __float2half(x2 - __half2float(h2));
                __half l3 = __float2half(x3 - __half2float(h3));
                *reinterpret_cast<uint32_t*>(Oh + (size_t)row0*DM + col) =
                    (uint32_t)__half_as_ushort(h0) | ((uint32_t)__half_as_ushort(h1)<<16);
                *reinterpret_cast<uint32_t*>(Ol + (size_t)row0*DM + col) =
                    (uint32_t)__half_as_ushort(l0) | ((uint32_t)__half_as_ushort(l1)<<16);
                *reinterpret_cast<uint32_t*>(Oh + (size_t)(row0+8)*DM + col) =
                    (uint32_t)__half_as_ushort(h2) | ((uint32_t)__half_as_ushort(h3)<<16);
                *reinterpret_cast<uint32_t*>(Ol + (size_t)(row0+8)*DM + col) =
                    (uint32_t)__half_as_ushort(l2) | ((uint32_t)__half_as_ushort(l3)<<16);
            }
        }
    }
}

// ---------------- GEMM wrappers ----------------------------------------------
__global__ void __launch_bounds__(NTHR, 2) proj_mma(
    const float* __restrict__ bq, const float* __restrict__ bk, const float* __restrict__ bv,
    const float* __restrict__ gamma)
{
    const int z = blockIdx.z;
    if (z == 0){
        gemm_core<1>(g_inh[0], g_inl[0], g_w[0], bq, gamma,
                     nullptr, g_qnh, g_qnl, blockIdx.y * BM, blockIdx.x * BN);
    } else {
        const float* bias = (z == 1) ? bk : bv;
        gemm_core<0>(g_inh[z], g_inl[z], g_w[z], bias, nullptr,
                     g_kvin[z-1], nullptr, nullptr, blockIdx.y * BM, blockIdx.x * BN);
    }
}
__global__ void __launch_bounds__(NTHR, 2) out_mma(
    const float* __restrict__ bo, float* __restrict__ out)
{
    const int b = blockIdx.z;
    gemm_core<0>(g_qnh + (size_t)b*SEQ*DM, g_qnl + (size_t)b*SEQ*DM,
                 g_w2 + (size_t)b*DM*DM, bo, nullptr,
                 out + (size_t)b*SEQ*DM, nullptr, nullptr,
                 blockIdx.y * BM, blockIdx.x * BN);
}

// ---------------- split / convert kernels --------------------------------------
__global__ void __launch_bounds__(256) split_in(
    const float* __restrict__ q, const float* __restrict__ k, const float* __restrict__ v)
{
    int z = blockIdx.z;
    const float* s = (z == 0) ? q : (z == 1) ? k : v;
    size_t i4 = (size_t)blockIdx.x * 256 + threadIdx.x;
    float4 x = *reinterpret_cast<const float4*>(s + i4*4);
    store_hl(&g_inh[z][i4*4], &g_inl[z][i4*4], x);
}
__global__ void __launch_bounds__(256) conv_w(
    const float* __restrict__ wq, const float* __restrict__ wk, const float* __restrict__ wv)
{
    int z = blockIdx.z;
    const float* s = (z == 0) ? wq : (z == 1) ? wk : wv;
    size_t i4 = (size_t)blockIdx.x * 256 + threadIdx.x;
    float4 x = *reinterpret_cast<const float4*>(s + i4*4);
    __half h[4] = {__float2half(x.x), __float2half(x.y), __float2half(x.z), __float2half(x.w)};
    *reinterpret_cast<uint2*>(&g_w[z][i4*4]) = make_uint2(
        (uint32_t)__half_as_ushort(h[0]) | ((uint32_t)__half_as_ushort(h[1])<<16),
        (uint32_t)__half_as_ushort(h[2]) | ((uint32_t)__half_as_ushort(h[3])<<16));
}

// ---------------- kv accumulation ----------------------------------------------
__global__ void zero_kv(){
    int i = blockIdx.x * 256 + threadIdx.x;
    if (i < BATCH*H*64*64) g_kv[i] = 0.f;
}
__global__ void __launch_bounds__(256) kv_kernel()
{
    const int bh = blockIdx.x, chunk = blockIdx.y;
    const int b = bh >> 4, h = bh & 15;
    const float* kbase = g_kvin[0] + (size_t)b*SEQ*DM + h*64;
    const float* vbase = g_kvin[1] + (size_t)b*SEQ*DM + h*64;
    __shared__ float ks[8][64], vs[8][64];
    const int tid = threadIdx.x;
    const int tj = tid & 15, ti = tid >> 4;
    float acc[4][4];
#pragma unroll
    for (int i = 0; i < 4; i++)
#pragma unroll
        for (int j = 0; j < 4; j++) acc[i][j] = 0.f;
    const int n0 = chunk * (SEQ/16);
    for (int nn = n0; nn < n0 + SEQ/16; nn += 8){
        int l = tid & 127, row = l >> 4, c = (l & 15) << 2;
        const float* src = (tid < 128) ? kbase : vbase;
        float* dst = (tid < 128) ? &ks[row][c] : &vs[row][c];
        *reinterpret_cast<float4*>(dst) =
            *reinterpret_cast<const float4*>(src + (size_t)(nn+row)*DM + c);
        __syncthreads();
#pragma unroll
        for (int r = 0; r < 8; r++){
            float kr[4], vr[4];
            *reinterpret_cast<float4*>(kr) = *reinterpret_cast<const float4*>(&ks[r][ti*4]);
            *reinterpret_cast<float4*>(vr) = *reinterpret_cast<const float4*>(&vs[r][tj*4]);
#pragma unroll
            for (int i = 0; i < 4; i++)
#pragma unroll
                for (int j = 0; j < 4; j++) acc[i][j] += kr[i] * vr[j];
        }
        __syncthreads();
    }
    float* kvp = g_kv + (size_t)bh * 4096;
#pragma unroll
    for (int i = 0; i < 4; i++)
#pragma unroll
        for (int j = 0; j < 4; j++)
            atomicAdd(&kvp[(ti*4+i)*64 + tj*4 + j], acc[i][j]);
}

// ---------------- fold: xnorm(kv) @ Wo^T -> W2 (fp16) --------------------------
__global__ void __launch_bounds__(256) fold_kernel(
    const float* __restrict__ Wo, const float* __restrict__ gamma)
{
    const int bh = blockIdx.x, jc = blockIdx.y;
    const int b = bh >> 4, h = bh & 15;
    const int j0 = jc * 128;
    __shared__ float kvn[64][65];
    __shared__ float rn[64];
    const int tid = threadIdx.x;
    const float* kvsrc = g_kv + (size_t)bh * 4096;
    for (int l = tid; l < 4096; l += 256) kvn[l>>6][l&63] = kvsrc[l];
    __syncthreads();
    if (tid < 64){
        float s = 0.f;
#pragma unroll 16
        for (int d = 0; d < 64; d++){ float x = kvn[tid][d]; s += x*x; }
        rn[tid] = gamma[h] * rsqrtf(s);
    }
    __syncthreads();
    const int i = tid & 63, jg = tid >> 6;
    const float sc = rn[i];
    __half* w2 = g_w2 + (size_t)b*DM*DM;
    for (int j = jg; j < 128; j += 4){
        const float* wr = Wo + (size_t)(j0+j)*DM + h*64;
        float acc = 0.f;
#pragma unroll 16
        for (int d = 0; d < 64; d++) acc += kvn[i][d] * __ldg(wr + d);
        w2[(size_t)(j0+j)*DM + h*64 + i] = __float2half(acc * sc);
    }
}

// ---------------- launch ----------------------------------------------------------
extern "C" void kernel_launch(void* const* d_in, const int* in_sizes, int n_in,
                              void* d_out, int out_size)
{
    const float* queries = (const float*)d_in[0];
    const float* keys    = (const float*)d_in[1];
    const float* values  = (const float*)d_in[2];
    const float* Wq = (const float*)d_in[3];
    const float* bq = (const float*)d_in[4];
    const float* Wk = (const float*)d_in[5];
    const float* bk = (const float*)d_in[6];
    const float* Wv = (const float*)d_in[7];
    const float* bv = (const float*)d_in[8];
    const float* Wo = (const float*)d_in[9];
    const float* bo = (const float*)d_in[10];
    const float* gamma = (const float*)d_in[11];
    float* out = (float*)d_out;

    cudaFuncSetAttribute(proj_mma, cudaFuncAttributeMaxDynamicSharedMemorySize, DYN);
    cudaFuncSetAttribute(out_mma,  cudaFuncAttributeMaxDynamicSharedMemorySize, DYN);

    split_in<<<dim3((MTOT*DM/4)/256, 1, 3), 256>>>(queries, keys, values);
    conv_w<<<dim3((DM*DM/4)/256, 1, 3), 256>>>(Wq, Wk, Wv);
    zero_kv<<<(BATCH*H*64*64)/256, 256>>>();

    proj_mma<<<dim3(DM/BN, MTOT/BM, 3), NTHR, DYN>>>(bq, bk, bv, gamma);

    kv_kernel<<<dim3(BATCH*H, 16), 256>>>();
    fold_kernel<<<dim3(BATCH*H, 8), 256>>>(Wo, gamma);

    out_mma<<<dim3(DM/BN, SEQ/BM, BATCH), NTHR, DYN>>>(bo, out);
}

// round 11
// speedup vs baseline: 5.5447x; 1.6095x over previous
#include <cuda_runtime.h>
#include <cuda_fp16.h>
#include <cstdint>

#define DM 1024
#define H 16
#define BATCH 4
#define SEQ 8192
#define MTOT (BATCH*SEQ)

// GEMM tiling: CTA 128x128, warp 32x64 (4M x 2N warps, 256 threads), 2 CTAs/SM
#define BM 128
#define BN 128
#define BK 64
#define NCH (DM/BK)             // 16 K-chunks
#define LDS_ 72                 // 64 + 8 pad elems -> 144B row stride
#define TB (128*LDS_*2)         // 18432 B per operand tile (128 rows)
#define STAGE_B (2*TB)          // 36864 B (A, B)
#define NSTG 2
#define DYN (NSTG*STAGE_B)      // 73728 B -> 2 CTAs per SM
#define NTHR 256

// ---------------- scratch ----------------------------------------------------
__device__ float g_kvin[2][(size_t)MTOT*DM];                  // k, v fp32
__device__ __half g_in[3][(size_t)MTOT*DM];                   // q,k,v fp16
__device__ __half g_w[3][DM*DM];
__device__ __half g_qn[(size_t)MTOT*DM];
__device__ __half g_w2[(size_t)BATCH*DM*DM];
__device__ float g_kv[BATCH*H*64*64];

// ---------------- helpers ------------------------------------------------------
static __device__ __forceinline__ uint32_t s2u(const void* p){
    uint32_t r;
    asm("{ .reg .u64 t; cvta.to.shared.u64 t, %1; cvt.u32.u64 %0, t; }" : "=r"(r) : "l"(p));
    return r;
}
static __device__ __forceinline__ void cp16(uint32_t dst, const void* src){
    asm volatile("cp.async.cg.shared.global [%0], [%1], 16;" :: "r"(dst), "l"(src));
}
#define CP_COMMIT() asm volatile("cp.async.commit_group;" ::: "memory")
#define LDM4(r, a) asm volatile( \
    "ldmatrix.sync.aligned.m8n8.x4.shared.b16 {%0,%1,%2,%3}, [%4];" \
    : "=r"((r)[0]),"=r"((r)[1]),"=r"((r)[2]),"=r"((r)[3]) : "r"(a))
#define MMA(d, a, b0_, b1_) asm volatile( \
    "mma.sync.aligned.m16n8k16.row.col.f32.f16.f16.f32 " \
    "{%0,%1,%2,%3},{%4,%5,%6,%7},{%8,%9},{%0,%1,%2,%3};" \
    : "+f"((d)[0]),"+f"((d)[1]),"+f"((d)[2]),"+f"((d)[3]) \
    : "r"((a)[0]),"r"((a)[1]),"r"((a)[2]),"r"((a)[3]), "r"(b0_),"r"(b1_))

// ---------------- fp16 single-pass GEMM core: C = A @ B^T + bias --------------
// EPI 0: bias + fp32 store.  EPI 1: bias + per-head xnorm + fp16 store.
template<int EPI>
static __device__ __forceinline__ void gemm_core(
    const __half* __restrict__ Ah,
    const __half* __restrict__ Bh,
    const float* __restrict__ bias, const float* __restrict__ gamma,
    float* __restrict__ C, __half* __restrict__ Oh,
    int bm, int bn)
{
    extern __shared__ __half smbuf[];
    const uint32_t smu = s2u(smbuf);
    const int tid  = threadIdx.x;
    const int lane = tid & 31;
    const int wid  = tid >> 5;
    const int wm   = wid & 3;        // 4 warps along M (32 rows)
    const int wn   = wid >> 2;       // 2 warps along N (64 cols)

    const uint32_t a_off = (uint32_t)((wm*32 + (lane & 15))*LDS_ + (lane >> 4)*8)*2;
    const uint32_t b_off = (uint32_t)TB +
                           (uint32_t)((wn*64 + (lane & 15))*LDS_ + (lane >> 4)*8)*2;

    float acc[2][8][4];
#pragma unroll
    for (int i = 0; i < 2; i++)
#pragma unroll
        for (int j = 0; j < 8; j++)
#pragma unroll
            for (int q = 0; q < 4; q++) acc[i][j][q] = 0.f;

#define ISSUE(c_) do {                                                         \
        const int c__ = (c_);                                                  \
        const uint32_t sb = smu + (uint32_t)((c__ & 1) * STAGE_B);             \
        const int k0 = c__ * BK;                                               \
        _Pragma("unroll")                                                      \
        for (int arr = 0; arr < 2; arr++){                                     \
            const __half* s = (arr==0)?Ah:Bh;                                  \
            const int row0 = (arr == 0) ? bm : bn;                             \
            const uint32_t ab = sb + (uint32_t)(arr * TB);                     \
            _Pragma("unroll")                                                  \
            for (int it = 0; it < 4; it++){                                    \
                int id = tid + it*NTHR;                                        \
                int r = id >> 3, cg = id & 7;                                  \
                cp16(ab + (uint32_t)(r*LDS_ + cg*8)*2,                         \
                     s + (size_t)(row0 + r)*DM + k0 + cg*8);                   \
            }                                                                  \
        }                                                                      \
        CP_COMMIT();                                                           \
    } while(0)

    ISSUE(0);
    for (int c = 0; c < NCH; c++){
        if (c + 1 < NCH){
            ISSUE(c + 1);
            asm volatile("cp.async.wait_group 1;" ::: "memory");
        } else {
            asm volatile("cp.async.wait_group 0;" ::: "memory");
        }
        __syncthreads();

        const uint32_t sb = smu + (uint32_t)((c & 1) * STAGE_B);
#pragma unroll
        for (int ks = 0; ks < 4; ks++){
            uint32_t bf[4][4];
#pragma unroll
            for (int np = 0; np < 4; np++)
                LDM4(bf[np], sb + b_off + (uint32_t)(np*16*LDS_ + ks*16)*2);
#pragma unroll
            for (int mt = 0; mt < 2; mt++){
                uint32_t af[4];
                LDM4(af, sb + a_off + (uint32_t)(mt*16*LDS_ + ks*16)*2);
#pragma unroll
                for (int nt = 0; nt < 8; nt++){
                    const int np = nt >> 1, sub = nt & 1;
                    MMA(acc[mt][nt], af, bf[np][sub], bf[np][sub+2]);
                }
            }
        }
        __syncthreads();
    }
#undef ISSUE

    // ---- epilogue ----
#pragma unroll
    for (int mt = 0; mt < 2; mt++){
        const int row0 = bm + wm*32 + mt*16 + (lane >> 2);
        if (EPI == 0){
#pragma unroll
            for (int nt = 0; nt < 8; nt++){
                const int col = bn + wn*64 + nt*8 + (lane & 3)*2;
                const float bx = bias[col], by = bias[col+1];
                float2 o0, o1;
                o0.x = acc[mt][nt][0] + bx;  o0.y = acc[mt][nt][1] + by;
                o1.x = acc[mt][nt][2] + bx;  o1.y = acc[mt][nt][3] + by;
                *reinterpret_cast<float2*>(C + (size_t)row0*DM + col) = o0;
                *reinterpret_cast<float2*>(C + (size_t)(row0+8)*DM + col) = o1;
            }
        } else {
            // per-head xnorm: this warp's 64 cols == one head
            float s0 = 0.f, s1 = 0.f;
#pragma unroll
            for (int nt = 0; nt < 8; nt++){
                const int col = bn + wn*64 + nt*8 + (lane & 3)*2;
                const float bx = bias[col], by = bias[col+1];
                acc[mt][nt][0] += bx; acc[mt][nt][1] += by;
                acc[mt][nt][2] += bx; acc[mt][nt][3] += by;
                s0 += acc[mt][nt][0]*acc[mt][nt][0] + acc[mt][nt][1]*acc[mt][nt][1];
                s1 += acc[mt][nt][2]*acc[mt][nt][2] + acc[mt][nt][3]*acc[mt][nt][3];
            }
            s0 += __shfl_xor_sync(0xffffffffu, s0, 1);
            s0 += __shfl_xor_sync(0xffffffffu, s0, 2);
            s1 += __shfl_xor_sync(0xffffffffu, s1, 1);
            s1 += __shfl_xor_sync(0xffffffffu, s1, 2);
            const int head = (bn >> 6) + wn;
            const float g = __ldg(gamma + head);
            const float sc0 = g * rsqrtf(s0);
            const float sc1 = g * rsqrtf(s1);
#pragma unroll
            for (int nt = 0; nt < 8; nt++){
                const int col = bn + wn*64 + nt*8 + (lane & 3)*2;
                __half h0 = __float2half(acc[mt][nt][0]*sc0);
                __half h1 = __float2half(acc[mt][nt][1]*sc0);
                __half h2 = __float2half(acc[mt][nt][2]*sc1);
                __half h3 = __float2half(acc[mt][nt][3]*sc1);
                *reinterpret_cast<uint32_t*>(Oh + (size_t)row0*DM + col) =
                    (uint32_t)__half_as_ushort(h0) | ((uint32_t)__half_as_ushort(h1)<<16);
                *reinterpret_cast<uint32_t*>(Oh + (size_t)(row0+8)*DM + col) =
                    (uint32_t)__half_as_ushort(h2) | ((uint32_t)__half_as_ushort(h3)<<16);
            }
        }
    }
}

// ---------------- GEMM wrappers ----------------------------------------------
__global__ void __launch_bounds__(NTHR, 2) proj_mma(
    const float* __restrict__ bq, const float* __restrict__ bk, const float* __restrict__ bv,
    const float* __restrict__ gamma)
{
    const int z = blockIdx.z;
    if (z == 0){
        gemm_core<1>(g_in[0], g_w[0], bq, gamma,
                     nullptr, g_qn, blockIdx.y * BM, blockIdx.x * BN);
    } else {
        const float* bias = (z == 1) ? bk : bv;
        gemm_core<0>(g_in[z], g_w[z], bias, nullptr,
                     g_kvin[z-1], nullptr, blockIdx.y * BM, blockIdx.x * BN);
    }
}
__global__ void __launch_bounds__(NTHR, 2) out_mma(
    const float* __restrict__ bo, float* __restrict__ out)
{
    const int b = blockIdx.z;
    gemm_core<0>(g_qn + (size_t)b*SEQ*DM,
                 g_w2 + (size_t)b*DM*DM, bo, nullptr,
                 out + (size_t)b*SEQ*DM, nullptr,
                 blockIdx.y * BM, blockIdx.x * BN);
}

// ---------------- convert kernels ----------------------------------------------
__global__ void __launch_bounds__(256) conv_in(
    const float* __restrict__ q, const float* __restrict__ k, const float* __restrict__ v)
{
    int z = blockIdx.z;
    const float* s = (z == 0) ? q : (z == 1) ? k : v;
    size_t i4 = (size_t)blockIdx.x * 256 + threadIdx.x;
    float4 x = *reinterpret_cast<const float4*>(s + i4*4);
    __half h[4] = {__float2half(x.x), __float2half(x.y), __float2half(x.z), __float2half(x.w)};
    *reinterpret_cast<uint2*>(&g_in[z][i4*4]) = make_uint2(
        (uint32_t)__half_as_ushort(h[0]) | ((uint32_t)__half_as_ushort(h[1])<<16),
        (uint32_t)__half_as_ushort(h[2]) | ((uint32_t)__half_as_ushort(h[3])<<16));
}
__global__ void __launch_bounds__(256) conv_w(
    const float* __restrict__ wq, const float* __restrict__ wk, const float* __restrict__ wv)
{
    int z = blockIdx.z;
    const float* s = (z == 0) ? wq : (z == 1) ? wk : wv;
    size_t i4 = (size_t)blockIdx.x * 256 + threadIdx.x;
    float4 x = *reinterpret_cast<const float4*>(s + i4*4);
    __half h[4] = {__float2half(x.x), __float2half(x.y), __float2half(x.z), __float2half(x.w)};
    *reinterpret_cast<uint2*>(&g_w[z][i4*4]) = make_uint2(
        (uint32_t)__half_as_ushort(h[0]) | ((uint32_t)__half_as_ushort(h[1])<<16),
        (uint32_t)__half_as_ushort(h[2]) | ((uint32_t)__half_as_ushort(h[3])<<16));
}

// ---------------- kv accumulation ----------------------------------------------
__global__ void zero_kv(){
    int i = blockIdx.x * 256 + threadIdx.x;
    if (i < BATCH*H*64*64) g_kv[i] = 0.f;
}
__global__ void __launch_bounds__(256) kv_kernel()
{
    const int bh = blockIdx.x, chunk = blockIdx.y;
    const int b = bh >> 4, h = bh & 15;
    const float* kbase = g_kvin[0] + (size_t)b*SEQ*DM + h*64;
    const float* vbase = g_kvin[1] + (size_t)b*SEQ*DM + h*64;
    __shared__ float ks[8][64], vs[8][64];
    const int tid = threadIdx.x;
    const int tj = tid & 15, ti = tid >> 4;
    float acc[4][4];
#pragma unroll
    for (int i = 0; i < 4; i++)
#pragma unroll
        for (int j = 0; j < 4; j++) acc[i][j] = 0.f;
    const int n0 = chunk * (SEQ/16);
    for (int nn = n0; nn < n0 + SEQ/16; nn += 8){
        int l = tid & 127, row = l >> 4, c = (l & 15) << 2;
        const float* src = (tid < 128) ? kbase : vbase;
        float* dst = (tid < 128) ? &ks[row][c] : &vs[row][c];
        *reinterpret_cast<float4*>(dst) =
            *reinterpret_cast<const float4*>(src + (size_t)(nn+row)*DM + c);
        __syncthreads();
#pragma unroll
        for (int r = 0; r < 8; r++){
            float kr[4], vr[4];
            *reinterpret_cast<float4*>(kr) = *reinterpret_cast<const float4*>(&ks[r][ti*4]);
            *reinterpret_cast<float4*>(vr) = *reinterpret_cast<const float4*>(&vs[r][tj*4]);
#pragma unroll
            for (int i = 0; i < 4; i++)
#pragma unroll
                for (int j = 0; j < 4; j++) acc[i][j] += kr[i] * vr[j];
        }
        __syncthreads();
    }
    float* kvp = g_kv + (size_t)bh * 4096;
#pragma unroll
    for (int i = 0; i < 4; i++)
#pragma unroll
        for (int j = 0; j < 4; j++)
            atomicAdd(&kvp[(ti*4+i)*64 + tj*4 + j], acc[i][j]);
}

// ---------------- fold: xnorm(kv) @ Wo^T -> W2 (fp16) --------------------------
__global__ void __launch_bounds__(256) fold_kernel(
    const float* __restrict__ Wo, const float* __restrict__ gamma)
{
    const int bh = blockIdx.x, jc = blockIdx.y;
    const int b = bh >> 4, h = bh & 15;
    const int j0 = jc * 128;
    __shared__ float kvn[64][65];
    __shared__ float rn[64];
    const int tid = threadIdx.x;
    const float* kvsrc = g_kv + (size_t)bh * 4096;
    for (int l = tid; l < 4096; l += 256) kvn[l>>6][l&63] = kvsrc[l];
    __syncthreads();
    if (tid < 64){
        float s = 0.f;
#pragma unroll 16
        for (int d = 0; d < 64; d++){ float x = kvn[tid][d]; s += x*x; }
        rn[tid] = gamma[h] * rsqrtf(s);
    }
    __syncthreads();
    const int i = tid & 63, jg = tid >> 6;
    const float sc = rn[i];
    __half* w2 = g_w2 + (size_t)b*DM*DM;
    for (int j = jg; j < 128; j += 4){
        const float* wr = Wo + (size_t)(j0+j)*DM + h*64;
        float acc = 0.f;
#pragma unroll 16
        for (int d = 0; d < 64; d++) acc += kvn[i][d] * __ldg(wr + d);
        w2[(size_t)(j0+j)*DM + h*64 + i] = __float2half(acc * sc);
    }
}

// ---------------- launch ----------------------------------------------------------
extern "C" void kernel_launch(void* const* d_in, const int* in_sizes, int n_in,
                              void* d_out, int out_size)
{
    const float* queries = (const float*)d_in[0];
    const float* keys    = (const float*)d_in[1];
    const float* values  = (const float*)d_in[2];
    const float* Wq = (const float*)d_in[3];
    const float* bq = (const float*)d_in[4];
    const float* Wk = (const float*)d_in[5];
    const float* bk = (const float*)d_in[6];
    const float* Wv = (const float*)d_in[7];
    const float* bv = (const float*)d_in[8];
    const float* Wo = (const float*)d_in[9];
    const float* bo = (const float*)d_in[10];
    const float* gamma = (const float*)d_in[11];
    float* out = (float*)d_out;

    cudaFuncSetAttribute(proj_mma, cudaFuncAttributeMaxDynamicSharedMemorySize, DYN);
    cudaFuncSetAttribute(out_mma,  cudaFuncAttributeMaxDynamicSharedMemorySize, DYN);

    conv_in<<<dim3((MTOT*DM/4)/256, 1, 3), 256>>>(queries, keys, values);
    conv_w<<<dim3((DM*DM/4)/256, 1, 3), 256>>>(Wq, Wk, Wv);
    zero_kv<<<(BATCH*H*64*64)/256, 256>>>();

    proj_mma<<<dim3(DM/BN, MTOT/BM, 3), NTHR, DYN>>>(bq, bk, bv, gamma);

    kv_kernel<<<dim3(BATCH*H, 16), 256>>>();
    fold_kernel<<<dim3(BATCH*H, 8), 256>>>(Wo, gamma);

    out_mma<<<dim3(DM/BN, SEQ/BM, BATCH), NTHR, DYN>>>(bo, out);
}